// round 1
// baseline (speedup 1.0000x reference)
#include <cuda_runtime.h>
#include <math.h>

#define Bn 4
#define Vn 50000
#define Cn 128
#define Kn 128
#define En 400000
#define Hn 128
#define BV (Bn * Vn)   // 200000 flat rows

// ---------------------------------------------------------------------------
// Scratch (device globals: no allocations allowed in kernel_launch)
// ---------------------------------------------------------------------------
__device__ __align__(16) float g_xspec[Bn * Kn * Cn];          // [B,K,C]
__device__ __align__(16) float g_xdiff[BV * Cn];               // [B,V,C]
__device__ __align__(16) float g_gx[BV * Cn];                  // [B,V,C]
__device__ __align__(16) float g_gy[BV * Cn];                  // [B,V,C]
__device__ __align__(16) float g_xgf[BV * Cn];                 // [B,V,C]
__device__ __align__(16) float g_h[BV * Hn];                   // [B,V,H]

// ---------------------------------------------------------------------------
// Zero kernels
// ---------------------------------------------------------------------------
__global__ void k_zero_spec() {
    int i = blockIdx.x * blockDim.x + threadIdx.x;
    if (i < Bn * Kn * Cn) g_xspec[i] = 0.f;
}

__global__ void k_zero_gxy() {
    size_t i = ((size_t)blockIdx.x * blockDim.x + threadIdx.x) * 4;
    if (i < (size_t)BV * Cn) {
        float4 z = make_float4(0.f, 0.f, 0.f, 0.f);
        *(float4*)(g_gx + i) = z;
        *(float4*)(g_gy + i) = z;
    }
}

// ---------------------------------------------------------------------------
// 1) Spectral projection: x_spec[b,k,c] = sum_v evecs[b,v,k] * mass[b,v]*x_in[b,v,c]
//    Outer-product accumulation over V chunks, atomicAdd partials.
//    256 threads: thread t owns k-block of 8 (t>>4) x c-block of 8 (t&15).
// ---------------------------------------------------------------------------
#define PROJ_VCHUNK 250
__global__ __launch_bounds__(256) void k_project(const float* __restrict__ x_in,
                                                 const float* __restrict__ mass,
                                                 const float* __restrict__ evecs) {
    const int b  = blockIdx.y;
    const int v0 = blockIdx.x * PROJ_VCHUNK;
    const int vend = min(v0 + PROJ_VCHUNK, Vn);
    const int t  = threadIdx.x;
    const int kg = (t >> 4) * 8;
    const int cg = (t & 15) * 8;

    __shared__ float se[Kn];
    __shared__ float sx[Cn];

    float acc[8][8];
#pragma unroll
    for (int i = 0; i < 8; i++)
#pragma unroll
        for (int j = 0; j < 8; j++) acc[i][j] = 0.f;

    for (int v = v0; v < vend; ++v) {
        __syncthreads();
        size_t rb = ((size_t)b * Vn + v) * 128;
        if (t < 128) {
            se[t] = evecs[rb + t];
        } else {
            int c = t - 128;
            sx[c] = mass[b * Vn + v] * x_in[rb + c];
        }
        __syncthreads();
        float e[8], xr[8];
#pragma unroll
        for (int i = 0; i < 8; i++) e[i] = se[kg + i];
#pragma unroll
        for (int j = 0; j < 8; j++) xr[j] = sx[cg + j];
#pragma unroll
        for (int i = 0; i < 8; i++)
#pragma unroll
            for (int j = 0; j < 8; j++) acc[i][j] += e[i] * xr[j];
    }

    float* dst = g_xspec + (size_t)b * Kn * Cn;
#pragma unroll
    for (int i = 0; i < 8; i++)
#pragma unroll
        for (int j = 0; j < 8; j++)
            atomicAdd(&dst[(kg + i) * Cn + (cg + j)], acc[i][j]);
}

// ---------------------------------------------------------------------------
// 2) Spectral decay: x_spec[b,k,c] *= exp(-evals[b,k] * max(t[c],1e-8))
// ---------------------------------------------------------------------------
__global__ void k_decay(const float* __restrict__ evals, const float* __restrict__ dt) {
    int i = blockIdx.x * blockDim.x + threadIdx.x;
    if (i >= Bn * Kn * Cn) return;
    int c = i & 127;
    int k = (i >> 7) & 127;
    int b = i >> 14;
    float t = fmaxf(dt[c], 1e-8f);
    g_xspec[i] *= expf(-evals[b * Kn + k] * t);
}

// ---------------------------------------------------------------------------
// Tiled fp32 GEMM building block: BM=64, BN=128, BK=16, 256 threads,
// per-thread 8 rows x 4 cols. Thread map: colg=(t&31)*4, rowg=(t>>5)*8.
// ---------------------------------------------------------------------------

// 3) x_diffuse[b] = evecs[b] (V x 128) @ x_spec[b] (128 x 128)
__global__ __launch_bounds__(256) void k_diffuse(const float* __restrict__ evecs) {
    const int b = blockIdx.y;
    const int row0 = blockIdx.x * 64;
    const float* __restrict__ A  = evecs + (size_t)b * Vn * Kn;
    const float* __restrict__ Bm = g_xspec + (size_t)b * Kn * Cn;
    float* __restrict__ Cp = g_xdiff + (size_t)b * Vn * Cn;

    __shared__ __align__(16) float sA[64 * 16];
    __shared__ __align__(16) float sB[16 * 128];

    const int t = threadIdx.x;
    const int colg = (t & 31) * 4;
    const int rowg = (t >> 5) * 8;
    const int lrow = t >> 2;
    const int lk = (t & 3) * 4;

    float acc[8][4];
#pragma unroll
    for (int i = 0; i < 8; i++) { acc[i][0] = acc[i][1] = acc[i][2] = acc[i][3] = 0.f; }

    for (int kt = 0; kt < 8; kt++) {
        int arow = row0 + lrow;
        float4 av = make_float4(0.f, 0.f, 0.f, 0.f);
        if (arow < Vn) av = *(const float4*)(A + (size_t)arow * 128 + kt * 16 + lk);
        __syncthreads();
        *(float4*)(sA + lrow * 16 + lk) = av;
#pragma unroll
        for (int q = 0; q < 2; q++) {
            int e = t * 2 + q;
            int br = e >> 5;
            int bc = (e & 31) * 4;
            *(float4*)(sB + br * 128 + bc) = *(const float4*)(Bm + (kt * 16 + br) * 128 + bc);
        }
        __syncthreads();
#pragma unroll
        for (int kk = 0; kk < 16; kk++) {
            float a[8];
#pragma unroll
            for (int i = 0; i < 8; i++) a[i] = sA[(rowg + i) * 16 + kk];
            float4 b4 = *(const float4*)(sB + kk * 128 + colg);
#pragma unroll
            for (int i = 0; i < 8; i++) {
                acc[i][0] += a[i] * b4.x; acc[i][1] += a[i] * b4.y;
                acc[i][2] += a[i] * b4.z; acc[i][3] += a[i] * b4.w;
            }
        }
    }
#pragma unroll
    for (int i = 0; i < 8; i++) {
        int r = row0 + rowg + i;
        if (r < Vn)
            *(float4*)(Cp + (size_t)r * 128 + colg) =
                make_float4(acc[i][0], acc[i][1], acc[i][2], acc[i][3]);
    }
}

// ---------------------------------------------------------------------------
// 4) SpMM scatter: gx[b,row] += vx * xdiff[b,col], gy[b,row] += vy * xdiff[b,col]
//    One warp per edge, lane = 4-channel chunk.
// ---------------------------------------------------------------------------
__global__ __launch_bounds__(256) void k_spmm(const int* __restrict__ rows,
                                              const int* __restrict__ cols,
                                              const float* __restrict__ xv,
                                              const float* __restrict__ yv) {
    long long w = (long long)blockIdx.x * (blockDim.x / 32) + (threadIdx.x >> 5);
    if (w >= (long long)Bn * En) return;
    const int lane = threadIdx.x & 31;
    const int b = (int)(w / En);
    const int be = (int)w;  // b*En + e
    const int col = cols[be];
    const int row = rows[be];
    const float vx = xv[be];
    const float vy = yv[be];

    float4 x4 = *(const float4*)(g_xdiff + ((size_t)b * Vn + col) * 128 + lane * 4);
    float* dx = g_gx + ((size_t)b * Vn + row) * 128 + lane * 4;
    float* dy = g_gy + ((size_t)b * Vn + row) * 128 + lane * 4;
    atomicAdd(dx + 0, vx * x4.x); atomicAdd(dx + 1, vx * x4.y);
    atomicAdd(dx + 2, vx * x4.z); atomicAdd(dx + 3, vx * x4.w);
    atomicAdd(dy + 0, vy * x4.x); atomicAdd(dy + 1, vy * x4.y);
    atomicAdd(dy + 2, vy * x4.z); atomicAdd(dy + 3, vy * x4.w);
}

// ---------------------------------------------------------------------------
// 5) Gradient features:
//    vB_re = gx@A_re - gy@A_im ;  vB_im = gy@A_re + gx@A_im
//    xgf = tanh(gx*vB_re + gy*vB_im)
//    Fused dual-accumulator GEMM over flat M = B*V (divisible by 64).
// ---------------------------------------------------------------------------
__global__ __launch_bounds__(256) void k_gradfeat(const float* __restrict__ A_re,
                                                  const float* __restrict__ A_im) {
    const size_t row0 = (size_t)blockIdx.x * 64;

    __shared__ __align__(16) float sGx[64 * 16];
    __shared__ __align__(16) float sGy[64 * 16];
    __shared__ __align__(16) float sRe[16 * 128];
    __shared__ __align__(16) float sIm[16 * 128];

    const int t = threadIdx.x;
    const int colg = (t & 31) * 4;
    const int rowg = (t >> 5) * 8;
    const int lrow = t >> 2;
    const int lk = (t & 3) * 4;

    float ar[8][4], ai[8][4];
#pragma unroll
    for (int i = 0; i < 8; i++)
#pragma unroll
        for (int j = 0; j < 4; j++) { ar[i][j] = 0.f; ai[i][j] = 0.f; }

    for (int kt = 0; kt < 8; kt++) {
        size_t arow = row0 + lrow;
        __syncthreads();
        *(float4*)(sGx + lrow * 16 + lk) = *(const float4*)(g_gx + arow * 128 + kt * 16 + lk);
        *(float4*)(sGy + lrow * 16 + lk) = *(const float4*)(g_gy + arow * 128 + kt * 16 + lk);
#pragma unroll
        for (int q = 0; q < 2; q++) {
            int e = t * 2 + q;
            int br = e >> 5;
            int bc = (e & 31) * 4;
            *(float4*)(sRe + br * 128 + bc) = *(const float4*)(A_re + (kt * 16 + br) * 128 + bc);
            *(float4*)(sIm + br * 128 + bc) = *(const float4*)(A_im + (kt * 16 + br) * 128 + bc);
        }
        __syncthreads();
#pragma unroll
        for (int kk = 0; kk < 16; kk++) {
            float ax[8], ay[8];
#pragma unroll
            for (int i = 0; i < 8; i++) {
                ax[i] = sGx[(rowg + i) * 16 + kk];
                ay[i] = sGy[(rowg + i) * 16 + kk];
            }
            float4 br4 = *(const float4*)(sRe + kk * 128 + colg);
            float4 bi4 = *(const float4*)(sIm + kk * 128 + colg);
#pragma unroll
            for (int i = 0; i < 8; i++) {
                ar[i][0] += ax[i] * br4.x - ay[i] * bi4.x;
                ar[i][1] += ax[i] * br4.y - ay[i] * bi4.y;
                ar[i][2] += ax[i] * br4.z - ay[i] * bi4.z;
                ar[i][3] += ax[i] * br4.w - ay[i] * bi4.w;
                ai[i][0] += ay[i] * br4.x + ax[i] * bi4.x;
                ai[i][1] += ay[i] * br4.y + ax[i] * bi4.y;
                ai[i][2] += ay[i] * br4.z + ax[i] * bi4.z;
                ai[i][3] += ay[i] * br4.w + ax[i] * bi4.w;
            }
        }
    }
#pragma unroll
    for (int i = 0; i < 8; i++) {
        size_t r = row0 + rowg + i;
        float4 gx4 = *(const float4*)(g_gx + r * 128 + colg);
        float4 gy4 = *(const float4*)(g_gy + r * 128 + colg);
        float4 o;
        o.x = tanhf(gx4.x * ar[i][0] + gy4.x * ai[i][0]);
        o.y = tanhf(gx4.y * ar[i][1] + gy4.y * ai[i][1]);
        o.z = tanhf(gx4.z * ar[i][2] + gy4.z * ai[i][2]);
        o.w = tanhf(gx4.w * ar[i][3] + gy4.w * ai[i][3]);
        *(float4*)(g_xgf + r * 128 + colg) = o;
    }
}

// ---------------------------------------------------------------------------
// 6) MLP layer 0: h = relu([x_in, x_diffuse, xgf] @ W0 + b0), K = 384
// ---------------------------------------------------------------------------
__global__ __launch_bounds__(256) void k_mlp0(const float* __restrict__ x_in,
                                              const float* __restrict__ W0,
                                              const float* __restrict__ b0) {
    const size_t row0 = (size_t)blockIdx.x * 64;

    __shared__ __align__(16) float sA[64 * 16];
    __shared__ __align__(16) float sB[16 * 128];

    const int t = threadIdx.x;
    const int colg = (t & 31) * 4;
    const int rowg = (t >> 5) * 8;
    const int lrow = t >> 2;
    const int lk = (t & 3) * 4;

    float acc[8][4];
#pragma unroll
    for (int i = 0; i < 8; i++) { acc[i][0] = acc[i][1] = acc[i][2] = acc[i][3] = 0.f; }

    for (int kt = 0; kt < 24; kt++) {
        int kbase = kt * 16;
        int region = kbase >> 7;  // 0: x_in, 1: x_diffuse, 2: xgf
        const float* base = (region == 0) ? x_in : ((region == 1) ? g_xdiff : g_xgf);
        int koff = kbase & 127;
        __syncthreads();
        *(float4*)(sA + lrow * 16 + lk) =
            *(const float4*)(base + (row0 + lrow) * 128 + koff + lk);
#pragma unroll
        for (int q = 0; q < 2; q++) {
            int e = t * 2 + q;
            int br = e >> 5;
            int bc = (e & 31) * 4;
            *(float4*)(sB + br * 128 + bc) = *(const float4*)(W0 + (size_t)(kbase + br) * 128 + bc);
        }
        __syncthreads();
#pragma unroll
        for (int kk = 0; kk < 16; kk++) {
            float a[8];
#pragma unroll
            for (int i = 0; i < 8; i++) a[i] = sA[(rowg + i) * 16 + kk];
            float4 b4 = *(const float4*)(sB + kk * 128 + colg);
#pragma unroll
            for (int i = 0; i < 8; i++) {
                acc[i][0] += a[i] * b4.x; acc[i][1] += a[i] * b4.y;
                acc[i][2] += a[i] * b4.z; acc[i][3] += a[i] * b4.w;
            }
        }
    }
    float4 bb = *(const float4*)(b0 + colg);
#pragma unroll
    for (int i = 0; i < 8; i++) {
        size_t r = row0 + rowg + i;
        float4 o;
        o.x = fmaxf(acc[i][0] + bb.x, 0.f);
        o.y = fmaxf(acc[i][1] + bb.y, 0.f);
        o.z = fmaxf(acc[i][2] + bb.z, 0.f);
        o.w = fmaxf(acc[i][3] + bb.w, 0.f);
        *(float4*)(g_h + r * 128 + colg) = o;
    }
}

// ---------------------------------------------------------------------------
// 7) MLP layer 1 + residual: out = h @ W1 + b1 + x_in
// ---------------------------------------------------------------------------
__global__ __launch_bounds__(256) void k_mlp1(const float* __restrict__ x_in,
                                              const float* __restrict__ W1,
                                              const float* __restrict__ b1,
                                              float* __restrict__ out) {
    const size_t row0 = (size_t)blockIdx.x * 64;

    __shared__ __align__(16) float sA[64 * 16];
    __shared__ __align__(16) float sB[16 * 128];

    const int t = threadIdx.x;
    const int colg = (t & 31) * 4;
    const int rowg = (t >> 5) * 8;
    const int lrow = t >> 2;
    const int lk = (t & 3) * 4;

    float acc[8][4];
#pragma unroll
    for (int i = 0; i < 8; i++) { acc[i][0] = acc[i][1] = acc[i][2] = acc[i][3] = 0.f; }

    for (int kt = 0; kt < 8; kt++) {
        __syncthreads();
        *(float4*)(sA + lrow * 16 + lk) =
            *(const float4*)(g_h + (row0 + lrow) * 128 + kt * 16 + lk);
#pragma unroll
        for (int q = 0; q < 2; q++) {
            int e = t * 2 + q;
            int br = e >> 5;
            int bc = (e & 31) * 4;
            *(float4*)(sB + br * 128 + bc) = *(const float4*)(W1 + (size_t)(kt * 16 + br) * 128 + bc);
        }
        __syncthreads();
#pragma unroll
        for (int kk = 0; kk < 16; kk++) {
            float a[8];
#pragma unroll
            for (int i = 0; i < 8; i++) a[i] = sA[(rowg + i) * 16 + kk];
            float4 b4 = *(const float4*)(sB + kk * 128 + colg);
#pragma unroll
            for (int i = 0; i < 8; i++) {
                acc[i][0] += a[i] * b4.x; acc[i][1] += a[i] * b4.y;
                acc[i][2] += a[i] * b4.z; acc[i][3] += a[i] * b4.w;
            }
        }
    }
    float4 bb = *(const float4*)(b1 + colg);
#pragma unroll
    for (int i = 0; i < 8; i++) {
        size_t r = row0 + rowg + i;
        float4 xi = *(const float4*)(x_in + r * 128 + colg);
        float4 o;
        o.x = acc[i][0] + bb.x + xi.x;
        o.y = acc[i][1] + bb.y + xi.y;
        o.z = acc[i][2] + bb.z + xi.z;
        o.w = acc[i][3] + bb.w + xi.w;
        *(float4*)(out + r * 128 + colg) = o;
    }
}

// ---------------------------------------------------------------------------
// Launch
// ---------------------------------------------------------------------------
extern "C" void kernel_launch(void* const* d_in, const int* in_sizes, int n_in,
                              void* d_out, int out_size) {
    const float* x_in  = (const float*)d_in[0];
    const float* mass  = (const float*)d_in[1];
    // d_in[2] = L (unused)
    const float* evals = (const float*)d_in[3];
    const float* evecs = (const float*)d_in[4];
    const int*   grows = (const int*)d_in[5];
    const int*   gcols = (const int*)d_in[6];
    const float* gxv   = (const float*)d_in[7];
    const float* gyv   = (const float*)d_in[8];
    const float* dt    = (const float*)d_in[9];
    const float* A_re  = (const float*)d_in[10];
    const float* A_im  = (const float*)d_in[11];
    const float* W0    = (const float*)d_in[12];
    const float* b0    = (const float*)d_in[13];
    const float* W1    = (const float*)d_in[14];
    const float* b1    = (const float*)d_in[15];
    float* out = (float*)d_out;

    // 1) spectral projection
    k_zero_spec<<<(Bn * Kn * Cn + 255) / 256, 256>>>();
    k_project<<<dim3((Vn + PROJ_VCHUNK - 1) / PROJ_VCHUNK, Bn), 256>>>(x_in, mass, evecs);
    // 2) decay
    k_decay<<<(Bn * Kn * Cn + 255) / 256, 256>>>(evals, dt);
    // 3) unproject
    k_diffuse<<<dim3((Vn + 63) / 64, Bn), 256>>>(evecs);
    // 4) sparse gradients
    k_zero_gxy<<<(BV * Cn / 4 + 255) / 256, 256>>>();
    {
        long long warps = (long long)Bn * En;
        int wpb = 256 / 32;
        int blocks = (int)((warps + wpb - 1) / wpb);
        k_spmm<<<blocks, 256>>>(grows, gcols, gxv, gyv);
    }
    // 5) gradient features
    k_gradfeat<<<BV / 64, 256>>>(A_re, A_im);
    // 6) MLP
    k_mlp0<<<BV / 64, 256>>>(x_in, W0, b0);
    k_mlp1<<<BV / 64, 256>>>(x_in, W1, b1, out);
}

// round 2
// speedup vs baseline: 1.2006x; 1.2006x over previous
#include <cuda_runtime.h>
#include <math.h>

#define Bn 4
#define Vn 50000
#define Cn 128
#define Kn 128
#define En 400000
#define Hn 128
#define BV (Bn * Vn)      // 200000 flat rows
#define BE (Bn * En)      // 1600000 edges
#define NSCAN 391         // ceil(BV / 512)

// ---------------------------------------------------------------------------
// Scratch (device globals: no allocations allowed in kernel_launch)
// ---------------------------------------------------------------------------
__device__ __align__(16) float g_xspec[Bn * Kn * Cn];          // [B,K,C]
__device__ __align__(16) float g_xdiff[BV * Cn];               // [B,V,C]
__device__ __align__(16) float g_gx[BV * Cn];                  // [B,V,C]
__device__ __align__(16) float g_gy[BV * Cn];                  // [B,V,C]
__device__ __align__(16) float g_xgf[BV * Cn];                 // [B,V,C]
__device__ __align__(16) float g_h[BV * Hn];                   // [B,V,H]

// CSR build scratch
__device__ int   g_cnt[BV];
__device__ int   g_off[BV];
__device__ int   g_cur[BV];
__device__ int   g_bsum[NSCAN];
__device__ int   g_scol[BE];
__device__ float g_svx[BE];
__device__ float g_svy[BE];

// ---------------------------------------------------------------------------
// Zero kernels
// ---------------------------------------------------------------------------
__global__ void k_zero_spec() {
    int i = blockIdx.x * blockDim.x + threadIdx.x;
    if (i < Bn * Kn * Cn) g_xspec[i] = 0.f;
}

__global__ void k_zero_cnt() {
    int i = blockIdx.x * blockDim.x + threadIdx.x;
    if (i < BV) g_cnt[i] = 0;
}

// ---------------------------------------------------------------------------
// 1) Spectral projection: x_spec[b,k,c] = sum_v evecs[b,v,k] * mass[b,v]*x_in[b,v,c]
// ---------------------------------------------------------------------------
#define PROJ_VCHUNK 250
__global__ __launch_bounds__(256) void k_project(const float* __restrict__ x_in,
                                                 const float* __restrict__ mass,
                                                 const float* __restrict__ evecs) {
    const int b  = blockIdx.y;
    const int v0 = blockIdx.x * PROJ_VCHUNK;
    const int vend = min(v0 + PROJ_VCHUNK, Vn);
    const int t  = threadIdx.x;
    const int kg = (t >> 4) * 8;
    const int cg = (t & 15) * 8;

    __shared__ float se[Kn];
    __shared__ float sx[Cn];

    float acc[8][8];
#pragma unroll
    for (int i = 0; i < 8; i++)
#pragma unroll
        for (int j = 0; j < 8; j++) acc[i][j] = 0.f;

    for (int v = v0; v < vend; ++v) {
        __syncthreads();
        size_t rb = ((size_t)b * Vn + v) * 128;
        if (t < 128) {
            se[t] = evecs[rb + t];
        } else {
            int c = t - 128;
            sx[c] = mass[b * Vn + v] * x_in[rb + c];
        }
        __syncthreads();
        float e[8], xr[8];
#pragma unroll
        for (int i = 0; i < 8; i++) e[i] = se[kg + i];
#pragma unroll
        for (int j = 0; j < 8; j++) xr[j] = sx[cg + j];
#pragma unroll
        for (int i = 0; i < 8; i++)
#pragma unroll
            for (int j = 0; j < 8; j++) acc[i][j] += e[i] * xr[j];
    }

    float* dst = g_xspec + (size_t)b * Kn * Cn;
#pragma unroll
    for (int i = 0; i < 8; i++)
#pragma unroll
        for (int j = 0; j < 8; j++)
            atomicAdd(&dst[(kg + i) * Cn + (cg + j)], acc[i][j]);
}

// ---------------------------------------------------------------------------
// 2) Spectral decay
// ---------------------------------------------------------------------------
__global__ void k_decay(const float* __restrict__ evals, const float* __restrict__ dt) {
    int i = blockIdx.x * blockDim.x + threadIdx.x;
    if (i >= Bn * Kn * Cn) return;
    int c = i & 127;
    int k = (i >> 7) & 127;
    int b = i >> 14;
    float t = fmaxf(dt[c], 1e-8f);
    g_xspec[i] *= expf(-evals[b * Kn + k] * t);
}

// ---------------------------------------------------------------------------
// 3) x_diffuse[b] = evecs[b] (V x 128) @ x_spec[b] (128 x 128)
// ---------------------------------------------------------------------------
__global__ __launch_bounds__(256) void k_diffuse(const float* __restrict__ evecs) {
    const int b = blockIdx.y;
    const int row0 = blockIdx.x * 64;
    const float* __restrict__ A  = evecs + (size_t)b * Vn * Kn;
    const float* __restrict__ Bm = g_xspec + (size_t)b * Kn * Cn;
    float* __restrict__ Cp = g_xdiff + (size_t)b * Vn * Cn;

    __shared__ __align__(16) float sA[64 * 16];
    __shared__ __align__(16) float sB[16 * 128];

    const int t = threadIdx.x;
    const int colg = (t & 31) * 4;
    const int rowg = (t >> 5) * 8;
    const int lrow = t >> 2;
    const int lk = (t & 3) * 4;

    float acc[8][4];
#pragma unroll
    for (int i = 0; i < 8; i++) { acc[i][0] = acc[i][1] = acc[i][2] = acc[i][3] = 0.f; }

    for (int kt = 0; kt < 8; kt++) {
        int arow = row0 + lrow;
        float4 av = make_float4(0.f, 0.f, 0.f, 0.f);
        if (arow < Vn) av = *(const float4*)(A + (size_t)arow * 128 + kt * 16 + lk);
        __syncthreads();
        *(float4*)(sA + lrow * 16 + lk) = av;
#pragma unroll
        for (int q = 0; q < 2; q++) {
            int e = t * 2 + q;
            int br = e >> 5;
            int bc = (e & 31) * 4;
            *(float4*)(sB + br * 128 + bc) = *(const float4*)(Bm + (kt * 16 + br) * 128 + bc);
        }
        __syncthreads();
#pragma unroll
        for (int kk = 0; kk < 16; kk++) {
            float a[8];
#pragma unroll
            for (int i = 0; i < 8; i++) a[i] = sA[(rowg + i) * 16 + kk];
            float4 b4 = *(const float4*)(sB + kk * 128 + colg);
#pragma unroll
            for (int i = 0; i < 8; i++) {
                acc[i][0] += a[i] * b4.x; acc[i][1] += a[i] * b4.y;
                acc[i][2] += a[i] * b4.z; acc[i][3] += a[i] * b4.w;
            }
        }
    }
#pragma unroll
    for (int i = 0; i < 8; i++) {
        int r = row0 + rowg + i;
        if (r < Vn)
            *(float4*)(Cp + (size_t)r * 128 + colg) =
                make_float4(acc[i][0], acc[i][1], acc[i][2], acc[i][3]);
    }
}

// ---------------------------------------------------------------------------
// 4) CSR build + gather SpMM (replaces atomic scatter)
// ---------------------------------------------------------------------------
__global__ __launch_bounds__(256) void k_hist(const int* __restrict__ rows) {
    int be = blockIdx.x * blockDim.x + threadIdx.x;
    if (be >= BE) return;
    int b = be / En;
    atomicAdd(&g_cnt[b * Vn + rows[be]], 1);
}

// block-level exclusive scan of 512 counts; block totals to g_bsum
__global__ __launch_bounds__(512) void k_scanA() {
    __shared__ int s[512];
    int t = threadIdx.x;
    int i = blockIdx.x * 512 + t;
    int v = (i < BV) ? g_cnt[i] : 0;
    s[t] = v;
    __syncthreads();
#pragma unroll
    for (int d = 1; d < 512; d <<= 1) {
        int x = (t >= d) ? s[t - d] : 0;
        __syncthreads();
        s[t] += x;
        __syncthreads();
    }
    if (i < BV) g_off[i] = s[t] - v;       // exclusive (local)
    if (t == 511) g_bsum[blockIdx.x] = s[511];
}

__global__ __launch_bounds__(512) void k_scanB() {
    __shared__ int s[512];
    int t = threadIdx.x;
    int v = (t < NSCAN) ? g_bsum[t] : 0;
    s[t] = v;
    __syncthreads();
#pragma unroll
    for (int d = 1; d < 512; d <<= 1) {
        int x = (t >= d) ? s[t - d] : 0;
        __syncthreads();
        s[t] += x;
        __syncthreads();
    }
    if (t < NSCAN) g_bsum[t] = s[t] - v;   // exclusive block bases
}

__global__ __launch_bounds__(512) void k_scanC() {
    int i = blockIdx.x * 512 + threadIdx.x;
    if (i >= BV) return;
    int o = g_off[i] + g_bsum[blockIdx.x];
    g_off[i] = o;
    g_cur[i] = o;
}

__global__ __launch_bounds__(256) void k_scatter(const int* __restrict__ rows,
                                                 const int* __restrict__ cols,
                                                 const float* __restrict__ xv,
                                                 const float* __restrict__ yv) {
    int be = blockIdx.x * blockDim.x + threadIdx.x;
    if (be >= BE) return;
    int b = be / En;
    int flat = b * Vn + rows[be];
    int pos = atomicAdd(&g_cur[flat], 1);
    g_scol[pos] = cols[be];
    g_svx[pos] = xv[be];
    g_svy[pos] = yv[be];
}

// one block (128 threads = channels) per output row; register accumulation
__global__ __launch_bounds__(128) void k_gather() {
    const int flat = blockIdx.x;
    const int b = flat / Vn;
    const int t = threadIdx.x;
    const int start = g_off[flat];
    const int n = g_cnt[flat];
    const float* __restrict__ xb = g_xdiff + (size_t)b * Vn * Cn;

    float ax = 0.f, ay = 0.f;
    int col = 0; float vx = 0.f, vy = 0.f;
    if (n > 0) { col = g_scol[start]; vx = g_svx[start]; vy = g_svy[start]; }
    for (int e = 0; e < n; e++) {
        int col2 = 0; float vx2 = 0.f, vy2 = 0.f;
        if (e + 1 < n) {
            col2 = g_scol[start + e + 1];
            vx2 = g_svx[start + e + 1];
            vy2 = g_svy[start + e + 1];
        }
        float x = xb[(size_t)col * Cn + t];
        ax = fmaf(vx, x, ax);
        ay = fmaf(vy, x, ay);
        col = col2; vx = vx2; vy = vy2;
    }
    g_gx[(size_t)flat * Cn + t] = ax;
    g_gy[(size_t)flat * Cn + t] = ay;
}

// ---------------------------------------------------------------------------
// 5) Gradient features (fused dual GEMM + tanh)
// ---------------------------------------------------------------------------
__global__ __launch_bounds__(256) void k_gradfeat(const float* __restrict__ A_re,
                                                  const float* __restrict__ A_im) {
    const size_t row0 = (size_t)blockIdx.x * 64;

    __shared__ __align__(16) float sGx[64 * 16];
    __shared__ __align__(16) float sGy[64 * 16];
    __shared__ __align__(16) float sRe[16 * 128];
    __shared__ __align__(16) float sIm[16 * 128];

    const int t = threadIdx.x;
    const int colg = (t & 31) * 4;
    const int rowg = (t >> 5) * 8;
    const int lrow = t >> 2;
    const int lk = (t & 3) * 4;

    float ar[8][4], ai[8][4];
#pragma unroll
    for (int i = 0; i < 8; i++)
#pragma unroll
        for (int j = 0; j < 4; j++) { ar[i][j] = 0.f; ai[i][j] = 0.f; }

    for (int kt = 0; kt < 8; kt++) {
        size_t arow = row0 + lrow;
        __syncthreads();
        *(float4*)(sGx + lrow * 16 + lk) = *(const float4*)(g_gx + arow * 128 + kt * 16 + lk);
        *(float4*)(sGy + lrow * 16 + lk) = *(const float4*)(g_gy + arow * 128 + kt * 16 + lk);
#pragma unroll
        for (int q = 0; q < 2; q++) {
            int e = t * 2 + q;
            int br = e >> 5;
            int bc = (e & 31) * 4;
            *(float4*)(sRe + br * 128 + bc) = *(const float4*)(A_re + (kt * 16 + br) * 128 + bc);
            *(float4*)(sIm + br * 128 + bc) = *(const float4*)(A_im + (kt * 16 + br) * 128 + bc);
        }
        __syncthreads();
#pragma unroll
        for (int kk = 0; kk < 16; kk++) {
            float ax[8], ay[8];
#pragma unroll
            for (int i = 0; i < 8; i++) {
                ax[i] = sGx[(rowg + i) * 16 + kk];
                ay[i] = sGy[(rowg + i) * 16 + kk];
            }
            float4 br4 = *(const float4*)(sRe + kk * 128 + colg);
            float4 bi4 = *(const float4*)(sIm + kk * 128 + colg);
#pragma unroll
            for (int i = 0; i < 8; i++) {
                ar[i][0] += ax[i] * br4.x - ay[i] * bi4.x;
                ar[i][1] += ax[i] * br4.y - ay[i] * bi4.y;
                ar[i][2] += ax[i] * br4.z - ay[i] * bi4.z;
                ar[i][3] += ax[i] * br4.w - ay[i] * bi4.w;
                ai[i][0] += ay[i] * br4.x + ax[i] * bi4.x;
                ai[i][1] += ay[i] * br4.y + ax[i] * bi4.y;
                ai[i][2] += ay[i] * br4.z + ax[i] * bi4.z;
                ai[i][3] += ay[i] * br4.w + ax[i] * bi4.w;
            }
        }
    }
#pragma unroll
    for (int i = 0; i < 8; i++) {
        size_t r = row0 + rowg + i;
        float4 gx4 = *(const float4*)(g_gx + r * 128 + colg);
        float4 gy4 = *(const float4*)(g_gy + r * 128 + colg);
        float4 o;
        o.x = tanhf(gx4.x * ar[i][0] + gy4.x * ai[i][0]);
        o.y = tanhf(gx4.y * ar[i][1] + gy4.y * ai[i][1]);
        o.z = tanhf(gx4.z * ar[i][2] + gy4.z * ai[i][2]);
        o.w = tanhf(gx4.w * ar[i][3] + gy4.w * ai[i][3]);
        *(float4*)(g_xgf + r * 128 + colg) = o;
    }
}

// ---------------------------------------------------------------------------
// 6) MLP layer 0: h = relu([x_in, x_diffuse, xgf] @ W0 + b0), K = 384
// ---------------------------------------------------------------------------
__global__ __launch_bounds__(256) void k_mlp0(const float* __restrict__ x_in,
                                              const float* __restrict__ W0,
                                              const float* __restrict__ b0) {
    const size_t row0 = (size_t)blockIdx.x * 64;

    __shared__ __align__(16) float sA[64 * 16];
    __shared__ __align__(16) float sB[16 * 128];

    const int t = threadIdx.x;
    const int colg = (t & 31) * 4;
    const int rowg = (t >> 5) * 8;
    const int lrow = t >> 2;
    const int lk = (t & 3) * 4;

    float acc[8][4];
#pragma unroll
    for (int i = 0; i < 8; i++) { acc[i][0] = acc[i][1] = acc[i][2] = acc[i][3] = 0.f; }

    for (int kt = 0; kt < 24; kt++) {
        int kbase = kt * 16;
        int region = kbase >> 7;
        const float* base = (region == 0) ? x_in : ((region == 1) ? g_xdiff : g_xgf);
        int koff = kbase & 127;
        __syncthreads();
        *(float4*)(sA + lrow * 16 + lk) =
            *(const float4*)(base + (row0 + lrow) * 128 + koff + lk);
#pragma unroll
        for (int q = 0; q < 2; q++) {
            int e = t * 2 + q;
            int br = e >> 5;
            int bc = (e & 31) * 4;
            *(float4*)(sB + br * 128 + bc) = *(const float4*)(W0 + (size_t)(kbase + br) * 128 + bc);
        }
        __syncthreads();
#pragma unroll
        for (int kk = 0; kk < 16; kk++) {
            float a[8];
#pragma unroll
            for (int i = 0; i < 8; i++) a[i] = sA[(rowg + i) * 16 + kk];
            float4 b4 = *(const float4*)(sB + kk * 128 + colg);
#pragma unroll
            for (int i = 0; i < 8; i++) {
                acc[i][0] += a[i] * b4.x; acc[i][1] += a[i] * b4.y;
                acc[i][2] += a[i] * b4.z; acc[i][3] += a[i] * b4.w;
            }
        }
    }
    float4 bb = *(const float4*)(b0 + colg);
#pragma unroll
    for (int i = 0; i < 8; i++) {
        size_t r = row0 + rowg + i;
        float4 o;
        o.x = fmaxf(acc[i][0] + bb.x, 0.f);
        o.y = fmaxf(acc[i][1] + bb.y, 0.f);
        o.z = fmaxf(acc[i][2] + bb.z, 0.f);
        o.w = fmaxf(acc[i][3] + bb.w, 0.f);
        *(float4*)(g_h + r * 128 + colg) = o;
    }
}

// ---------------------------------------------------------------------------
// 7) MLP layer 1 + residual: out = h @ W1 + b1 + x_in
// ---------------------------------------------------------------------------
__global__ __launch_bounds__(256) void k_mlp1(const float* __restrict__ x_in,
                                              const float* __restrict__ W1,
                                              const float* __restrict__ b1,
                                              float* __restrict__ out) {
    const size_t row0 = (size_t)blockIdx.x * 64;

    __shared__ __align__(16) float sA[64 * 16];
    __shared__ __align__(16) float sB[16 * 128];

    const int t = threadIdx.x;
    const int colg = (t & 31) * 4;
    const int rowg = (t >> 5) * 8;
    const int lrow = t >> 2;
    const int lk = (t & 3) * 4;

    float acc[8][4];
#pragma unroll
    for (int i = 0; i < 8; i++) { acc[i][0] = acc[i][1] = acc[i][2] = acc[i][3] = 0.f; }

    for (int kt = 0; kt < 8; kt++) {
        __syncthreads();
        *(float4*)(sA + lrow * 16 + lk) =
            *(const float4*)(g_h + (row0 + lrow) * 128 + kt * 16 + lk);
#pragma unroll
        for (int q = 0; q < 2; q++) {
            int e = t * 2 + q;
            int br = e >> 5;
            int bc = (e & 31) * 4;
            *(float4*)(sB + br * 128 + bc) = *(const float4*)(W1 + (size_t)(kt * 16 + br) * 128 + bc);
        }
        __syncthreads();
#pragma unroll
        for (int kk = 0; kk < 16; kk++) {
            float a[8];
#pragma unroll
            for (int i = 0; i < 8; i++) a[i] = sA[(rowg + i) * 16 + kk];
            float4 b4 = *(const float4*)(sB + kk * 128 + colg);
#pragma unroll
            for (int i = 0; i < 8; i++) {
                acc[i][0] += a[i] * b4.x; acc[i][1] += a[i] * b4.y;
                acc[i][2] += a[i] * b4.z; acc[i][3] += a[i] * b4.w;
            }
        }
    }
    float4 bb = *(const float4*)(b1 + colg);
#pragma unroll
    for (int i = 0; i < 8; i++) {
        size_t r = row0 + rowg + i;
        float4 xi = *(const float4*)(x_in + r * 128 + colg);
        float4 o;
        o.x = acc[i][0] + bb.x + xi.x;
        o.y = acc[i][1] + bb.y + xi.y;
        o.z = acc[i][2] + bb.z + xi.z;
        o.w = acc[i][3] + bb.w + xi.w;
        *(float4*)(out + r * 128 + colg) = o;
    }
}

// ---------------------------------------------------------------------------
// Launch
// ---------------------------------------------------------------------------
extern "C" void kernel_launch(void* const* d_in, const int* in_sizes, int n_in,
                              void* d_out, int out_size) {
    const float* x_in  = (const float*)d_in[0];
    const float* mass  = (const float*)d_in[1];
    // d_in[2] = L (unused)
    const float* evals = (const float*)d_in[3];
    const float* evecs = (const float*)d_in[4];
    const int*   grows = (const int*)d_in[5];
    const int*   gcols = (const int*)d_in[6];
    const float* gxv   = (const float*)d_in[7];
    const float* gyv   = (const float*)d_in[8];
    const float* dt    = (const float*)d_in[9];
    const float* A_re  = (const float*)d_in[10];
    const float* A_im  = (const float*)d_in[11];
    const float* W0    = (const float*)d_in[12];
    const float* b0    = (const float*)d_in[13];
    const float* W1    = (const float*)d_in[14];
    const float* b1    = (const float*)d_in[15];
    float* out = (float*)d_out;

    // CSR build can start immediately (independent of diffusion math)
    k_zero_cnt<<<(BV + 255) / 256, 256>>>();
    k_hist<<<(BE + 255) / 256, 256>>>(grows);
    k_scanA<<<NSCAN, 512>>>();
    k_scanB<<<1, 512>>>();
    k_scanC<<<NSCAN, 512>>>();
    k_scatter<<<(BE + 255) / 256, 256>>>(grows, gcols, gxv, gyv);

    // 1) spectral projection
    k_zero_spec<<<(Bn * Kn * Cn + 255) / 256, 256>>>();
    k_project<<<dim3((Vn + PROJ_VCHUNK - 1) / PROJ_VCHUNK, Bn), 256>>>(x_in, mass, evecs);
    // 2) decay
    k_decay<<<(Bn * Kn * Cn + 255) / 256, 256>>>(evals, dt);
    // 3) unproject
    k_diffuse<<<dim3((Vn + 63) / 64, Bn), 256>>>(evecs);
    // 4) sparse gradients (gather, no atomics)
    k_gather<<<BV, 128>>>();
    // 5) gradient features
    k_gradfeat<<<BV / 64, 256>>>(A_re, A_im);
    // 6) MLP
    k_mlp0<<<BV / 64, 256>>>(x_in, W0, b0);
    k_mlp1<<<BV / 64, 256>>>(x_in, W1, b1, out);
}

// round 4
// speedup vs baseline: 1.8540x; 1.5442x over previous
#include <cuda_runtime.h>
#include <mma.h>
#include <math.h>
#include <stdint.h>

using namespace nvcuda;

#define Bn 4
#define Vn 50000
#define Cn 128
#define Kn 128
#define En 400000
#define BV (Bn * Vn)      // 200000
#define BE (Bn * En)      // 1600000
#define NSCAN 391
#define GRIDM 1563        // ceil(BV/128)
#define GRIDV 391         // ceil(Vn/128)
#define PROJ_VT 1024
#define GRIDP 49          // ceil(Vn/PROJ_VT)

// smem strides (floats)
#define LDA 36
#define LDB 136
#define LDE 132
#define LDC 132
#define SM_A (128 * LDA * 4)   // 18432 B
#define SM_B (32  * LDB * 4)   // 17408 B
#define SM_E (32  * LDE * 4)   // 16896 B
#define SM_C (128 * LDC * 4)   // 67584 B
#define SMEM_NORM SM_C               // mainloop (35840) fits under epilogue buf
#define SMEM_GRAD (2 * SM_C)         // 135168; mainloop needs 71680

typedef wmma::fragment<wmma::matrix_a, 16, 16, 8, wmma::precision::tf32, wmma::row_major> FragA;
typedef wmma::fragment<wmma::matrix_a, 16, 16, 8, wmma::precision::tf32, wmma::col_major> FragAT;
typedef wmma::fragment<wmma::matrix_b, 16, 16, 8, wmma::precision::tf32, wmma::row_major> FragB;
typedef wmma::fragment<wmma::accumulator, 16, 16, 8, float> FragC;

// ---------------------------------------------------------------------------
// Scratch
// ---------------------------------------------------------------------------
__device__ __align__(16) float g_xspec[Bn * Kn * Cn];
__device__ __align__(16) float g_xdiff[(size_t)BV * Cn];
__device__ __align__(16) float g_gx[(size_t)BV * Cn];
__device__ __align__(16) float g_gy[(size_t)BV * Cn];
__device__ __align__(16) float g_xgf[(size_t)BV * Cn];
__device__ __align__(16) float g_h[(size_t)BV * Cn];

__device__ int   g_cnt[BV];
__device__ int   g_off[BV];
__device__ int   g_cur[BV];
__device__ int   g_bsum[NSCAN];
__device__ int   g_scol[BE];
__device__ float g_svx[BE];
__device__ float g_svy[BE];

// ---------------------------------------------------------------------------
// helpers
// ---------------------------------------------------------------------------
__device__ __forceinline__ float to_tf32(float x) { return wmma::__float_to_tf32(x); }

// load 128 rows x 32 cols (row-major, ld floats) -> sA[128][LDA], tf32
__device__ __forceinline__ void ldA(float* sA, const float* __restrict__ g,
                                    int ld, int rows_valid, int tid) {
#pragma unroll
    for (int it = 0; it < 4; it++) {
        int idx = tid + it * 256;
        int r = idx >> 3, c4 = (idx & 7) << 2;
        float4 v = make_float4(0.f, 0.f, 0.f, 0.f);
        if (r < rows_valid) v = *(const float4*)(g + (size_t)r * ld + c4);
        *(float4*)(sA + r * LDA + c4) =
            make_float4(to_tf32(v.x), to_tf32(v.y), to_tf32(v.z), to_tf32(v.w));
    }
}

// load 32 rows x 128 cols (row-major, ld floats) -> sB[32][LDB], tf32
__device__ __forceinline__ void ldB(float* sB, const float* __restrict__ g,
                                    int ld, int tid) {
#pragma unroll
    for (int it = 0; it < 4; it++) {
        int idx = tid + it * 256;
        int r = idx >> 5, c4 = (idx & 31) << 2;
        float4 v = *(const float4*)(g + (size_t)r * ld + c4);
        *(float4*)(sB + r * LDB + c4) =
            make_float4(to_tf32(v.x), to_tf32(v.y), to_tf32(v.z), to_tf32(v.w));
    }
}

// ---------------------------------------------------------------------------
// zero kernels
// ---------------------------------------------------------------------------
__global__ void k_zero_spec() {
    int i = blockIdx.x * blockDim.x + threadIdx.x;
    if (i < Bn * Kn * Cn) g_xspec[i] = 0.f;
}
__global__ void k_zero_cnt() {
    int i = blockIdx.x * blockDim.x + threadIdx.x;
    if (i < BV) g_cnt[i] = 0;
}

// ---------------------------------------------------------------------------
// 1) projection (WMMA tf32): x_spec[b] += E_chunk^T @ (mass*x)_chunk
// ---------------------------------------------------------------------------
__global__ __launch_bounds__(256) void k_project(const float* __restrict__ x_in,
                                                 const float* __restrict__ mass,
                                                 const float* __restrict__ evecs) {
    extern __shared__ __align__(16) char sm[];
    float* sE = (float*)sm;
    float* sX = (float*)(sm + SM_E);
    float* sC = (float*)sm;
    const int tid = threadIdx.x, wid = tid >> 5;
    const int wm = wid & 3, wn = wid >> 2;
    const int b = blockIdx.y;
    const int v0 = blockIdx.x * PROJ_VT;
    const int vend = min(v0 + PROJ_VT, Vn);

    FragC cf[2][4];
#pragma unroll
    for (int i = 0; i < 2; i++)
#pragma unroll
        for (int j = 0; j < 4; j++) wmma::fill_fragment(cf[i][j], 0.f);

    for (int vc = v0; vc < vend; vc += 32) {
        __syncthreads();
#pragma unroll
        for (int it = 0; it < 4; it++) {
            int idx = tid + it * 256;
            int r = idx >> 5, c4 = (idx & 31) << 2;
            int v = vc + r;
            float4 e4 = make_float4(0.f, 0.f, 0.f, 0.f);
            float4 x4 = make_float4(0.f, 0.f, 0.f, 0.f);
            if (v < Vn) {
                size_t base = ((size_t)b * Vn + v) * 128 + c4;
                e4 = *(const float4*)(evecs + base);
                float m = mass[b * Vn + v];
                x4 = *(const float4*)(x_in + base);
                x4.x *= m; x4.y *= m; x4.z *= m; x4.w *= m;
            }
            *(float4*)(sE + r * LDE + c4) =
                make_float4(to_tf32(e4.x), to_tf32(e4.y), to_tf32(e4.z), to_tf32(e4.w));
            *(float4*)(sX + r * LDB + c4) =
                make_float4(to_tf32(x4.x), to_tf32(x4.y), to_tf32(x4.z), to_tf32(x4.w));
        }
        __syncthreads();
#pragma unroll
        for (int kk = 0; kk < 4; kk++) {
            FragAT af[2];
            FragB bf[4];
#pragma unroll
            for (int i = 0; i < 2; i++)
                wmma::load_matrix_sync(af[i], sE + kk * 8 * LDE + wm * 32 + i * 16, LDE);
#pragma unroll
            for (int j = 0; j < 4; j++)
                wmma::load_matrix_sync(bf[j], sX + kk * 8 * LDB + wn * 64 + j * 16, LDB);
#pragma unroll
            for (int i = 0; i < 2; i++)
#pragma unroll
                for (int j = 0; j < 4; j++)
                    wmma::mma_sync(cf[i][j], af[i], bf[j], cf[i][j]);
        }
    }
    __syncthreads();
#pragma unroll
    for (int i = 0; i < 2; i++)
#pragma unroll
        for (int j = 0; j < 4; j++)
            wmma::store_matrix_sync(sC + (wm * 32 + i * 16) * LDC + wn * 64 + j * 16,
                                    cf[i][j], LDC, wmma::mem_row_major);
    __syncthreads();
    float* dst = g_xspec + (size_t)b * 16384;
#pragma unroll
    for (int it = 0; it < 16; it++) {
        int idx = tid + it * 256;
        int r = idx >> 5, c4 = (idx & 31) << 2;
        float4 v = *(float4*)(sC + r * LDC + c4);
        atomicAdd(&dst[r * 128 + c4 + 0], v.x);
        atomicAdd(&dst[r * 128 + c4 + 1], v.y);
        atomicAdd(&dst[r * 128 + c4 + 2], v.z);
        atomicAdd(&dst[r * 128 + c4 + 3], v.w);
    }
}

// ---------------------------------------------------------------------------
// 2) decay (in place)
// ---------------------------------------------------------------------------
__global__ void k_decay(const float* __restrict__ evals, const float* __restrict__ dt) {
    int i = blockIdx.x * blockDim.x + threadIdx.x;
    if (i >= Bn * Kn * Cn) return;
    int c = i & 127, k = (i >> 7) & 127, b = i >> 14;
    float t = fmaxf(dt[c], 1e-8f);
    g_xspec[i] *= expf(-evals[b * 128 + k] * t);
}

// ---------------------------------------------------------------------------
// 3) diffuse (WMMA): xdiff = evecs @ xspec
// ---------------------------------------------------------------------------
__global__ __launch_bounds__(256) void g_diffuse(const float* __restrict__ evecs) {
    extern __shared__ __align__(16) char sm[];
    float* sA = (float*)sm;
    float* sB = (float*)(sm + SM_A);
    float* sC = (float*)sm;
    const int tid = threadIdx.x, wid = tid >> 5;
    const int wm = wid & 3, wn = wid >> 2;
    const int b = blockIdx.y;
    const int row0 = blockIdx.x * 128;
    const int rows_valid = min(128, Vn - row0);
    const float* A = evecs + ((size_t)b * Vn + row0) * 128;
    const float* Bp = g_xspec + (size_t)b * 16384;

    FragC cf[2][4];
#pragma unroll
    for (int i = 0; i < 2; i++)
#pragma unroll
        for (int j = 0; j < 4; j++) wmma::fill_fragment(cf[i][j], 0.f);

#pragma unroll
    for (int ck = 0; ck < 4; ck++) {
        __syncthreads();
        ldA(sA, A + ck * 32, 128, rows_valid, tid);
        ldB(sB, Bp + ck * 32 * 128, 128, tid);
        __syncthreads();
#pragma unroll
        for (int kk = 0; kk < 4; kk++) {
            FragA af[2];
            FragB bf[4];
#pragma unroll
            for (int i = 0; i < 2; i++)
                wmma::load_matrix_sync(af[i], sA + (wm * 32 + i * 16) * LDA + kk * 8, LDA);
#pragma unroll
            for (int j = 0; j < 4; j++)
                wmma::load_matrix_sync(bf[j], sB + kk * 8 * LDB + wn * 64 + j * 16, LDB);
#pragma unroll
            for (int i = 0; i < 2; i++)
#pragma unroll
                for (int j = 0; j < 4; j++)
                    wmma::mma_sync(cf[i][j], af[i], bf[j], cf[i][j]);
        }
    }
    __syncthreads();
#pragma unroll
    for (int i = 0; i < 2; i++)
#pragma unroll
        for (int j = 0; j < 4; j++)
            wmma::store_matrix_sync(sC + (wm * 32 + i * 16) * LDC + wn * 64 + j * 16,
                                    cf[i][j], LDC, wmma::mem_row_major);
    __syncthreads();
    float* outp = g_xdiff + ((size_t)b * Vn + row0) * 128;
#pragma unroll
    for (int it = 0; it < 16; it++) {
        int idx = tid + it * 256;
        int r = idx >> 5, c4 = (idx & 31) << 2;
        if (r < rows_valid)
            *(float4*)(outp + (size_t)r * 128 + c4) = *(float4*)(sC + r * LDC + c4);
    }
}

// ---------------------------------------------------------------------------
// 4) CSR build + gather SpMM (unchanged from R2)
// ---------------------------------------------------------------------------
__global__ __launch_bounds__(256) void k_hist(const int* __restrict__ rows) {
    int be = blockIdx.x * blockDim.x + threadIdx.x;
    if (be >= BE) return;
    int b = be / En;
    atomicAdd(&g_cnt[b * Vn + rows[be]], 1);
}
__global__ __launch_bounds__(512) void k_scanA() {
    __shared__ int s[512];
    int t = threadIdx.x;
    int i = blockIdx.x * 512 + t;
    int v = (i < BV) ? g_cnt[i] : 0;
    s[t] = v;
    __syncthreads();
#pragma unroll
    for (int d = 1; d < 512; d <<= 1) {
        int x = (t >= d) ? s[t - d] : 0;
        __syncthreads(); s[t] += x; __syncthreads();
    }
    if (i < BV) g_off[i] = s[t] - v;
    if (t == 511) g_bsum[blockIdx.x] = s[511];
}
__global__ __launch_bounds__(512) void k_scanB() {
    __shared__ int s[512];
    int t = threadIdx.x;
    int v = (t < NSCAN) ? g_bsum[t] : 0;
    s[t] = v;
    __syncthreads();
#pragma unroll
    for (int d = 1; d < 512; d <<= 1) {
        int x = (t >= d) ? s[t - d] : 0;
        __syncthreads(); s[t] += x; __syncthreads();
    }
    if (t < NSCAN) g_bsum[t] = s[t] - v;
}
__global__ __launch_bounds__(512) void k_scanC() {
    int i = blockIdx.x * 512 + threadIdx.x;
    if (i >= BV) return;
    int o = g_off[i] + g_bsum[blockIdx.x];
    g_off[i] = o;
    g_cur[i] = o;
}
__global__ __launch_bounds__(256) void k_scatter(const int* __restrict__ rows,
                                                 const int* __restrict__ cols,
                                                 const float* __restrict__ xv,
                                                 const float* __restrict__ yv) {
    int be = blockIdx.x * blockDim.x + threadIdx.x;
    if (be >= BE) return;
    int b = be / En;
    int pos = atomicAdd(&g_cur[b * Vn + rows[be]], 1);
    g_scol[pos] = cols[be];
    g_svx[pos] = xv[be];
    g_svy[pos] = yv[be];
}
__global__ __launch_bounds__(128) void k_gather() {
    const int flat = blockIdx.x;
    const int b = flat / Vn;
    const int t = threadIdx.x;
    const int start = g_off[flat];
    const int n = g_cnt[flat];
    const float* __restrict__ xb = g_xdiff + (size_t)b * Vn * Cn;

    float ax = 0.f, ay = 0.f;
    int col = 0; float vx = 0.f, vy = 0.f;
    if (n > 0) { col = g_scol[start]; vx = g_svx[start]; vy = g_svy[start]; }
    for (int e = 0; e < n; e++) {
        int col2 = 0; float vx2 = 0.f, vy2 = 0.f;
        if (e + 1 < n) {
            col2 = g_scol[start + e + 1];
            vx2 = g_svx[start + e + 1];
            vy2 = g_svy[start + e + 1];
        }
        float x = xb[(size_t)col * Cn + t];
        ax = fmaf(vx, x, ax);
        ay = fmaf(vy, x, ay);
        col = col2; vx = vx2; vy = vy2;
    }
    g_gx[(size_t)flat * Cn + t] = ax;
    g_gy[(size_t)flat * Cn + t] = ay;
}

// ---------------------------------------------------------------------------
// 5) gradfeat (WMMA dual): re = gx@Are - gy@Aim; im = gy@Are + gx@Aim;
//    xgf = tanh(gx*re + gy*im)
// ---------------------------------------------------------------------------
__global__ __launch_bounds__(256) void g_gradfeat(const float* __restrict__ A_re,
                                                  const float* __restrict__ A_im) {
    extern __shared__ __align__(16) char sm[];
    float* sGx = (float*)sm;
    float* sGy = (float*)(sm + SM_A);
    float* sRe = (float*)(sm + 2 * SM_A);
    float* sIm = (float*)(sm + 2 * SM_A + SM_B);
    float* sCre = (float*)sm;
    float* sCim = (float*)(sm + SM_C);
    const int tid = threadIdx.x, wid = tid >> 5;
    const int wm = wid & 3, wn = wid >> 2;
    const size_t row0 = (size_t)blockIdx.x * 128;
    const int rows_valid = (int)min((size_t)128, (size_t)BV - row0);

    FragC cre[2][4], cim[2][4];
#pragma unroll
    for (int i = 0; i < 2; i++)
#pragma unroll
        for (int j = 0; j < 4; j++) {
            wmma::fill_fragment(cre[i][j], 0.f);
            wmma::fill_fragment(cim[i][j], 0.f);
        }

#pragma unroll
    for (int ck = 0; ck < 4; ck++) {
        __syncthreads();
        ldA(sGx, g_gx + row0 * 128 + ck * 32, 128, rows_valid, tid);
        ldA(sGy, g_gy + row0 * 128 + ck * 32, 128, rows_valid, tid);
        ldB(sRe, A_re + ck * 32 * 128, 128, tid);
        ldB(sIm, A_im + ck * 32 * 128, 128, tid);
        __syncthreads();
#pragma unroll
        for (int kk = 0; kk < 4; kk++) {
            FragA agx[2], agy[2], agyn[2];
            FragB bre[4], bim[4];
#pragma unroll
            for (int i = 0; i < 2; i++) {
                wmma::load_matrix_sync(agx[i], sGx + (wm * 32 + i * 16) * LDA + kk * 8, LDA);
                wmma::load_matrix_sync(agy[i], sGy + (wm * 32 + i * 16) * LDA + kk * 8, LDA);
#pragma unroll
                for (int e = 0; e < agy[i].num_elements; e++) agyn[i].x[e] = -agy[i].x[e];
            }
#pragma unroll
            for (int j = 0; j < 4; j++) {
                wmma::load_matrix_sync(bre[j], sRe + kk * 8 * LDB + wn * 64 + j * 16, LDB);
                wmma::load_matrix_sync(bim[j], sIm + kk * 8 * LDB + wn * 64 + j * 16, LDB);
            }
#pragma unroll
            for (int i = 0; i < 2; i++)
#pragma unroll
                for (int j = 0; j < 4; j++) {
                    wmma::mma_sync(cre[i][j], agx[i],  bre[j], cre[i][j]);
                    wmma::mma_sync(cre[i][j], agyn[i], bim[j], cre[i][j]);
                    wmma::mma_sync(cim[i][j], agy[i],  bre[j], cim[i][j]);
                    wmma::mma_sync(cim[i][j], agx[i],  bim[j], cim[i][j]);
                }
        }
    }
    __syncthreads();
#pragma unroll
    for (int i = 0; i < 2; i++)
#pragma unroll
        for (int j = 0; j < 4; j++) {
            wmma::store_matrix_sync(sCre + (wm * 32 + i * 16) * LDC + wn * 64 + j * 16,
                                    cre[i][j], LDC, wmma::mem_row_major);
            wmma::store_matrix_sync(sCim + (wm * 32 + i * 16) * LDC + wn * 64 + j * 16,
                                    cim[i][j], LDC, wmma::mem_row_major);
        }
    __syncthreads();
#pragma unroll
    for (int it = 0; it < 16; it++) {
        int idx = tid + it * 256;
        int r = idx >> 5, c4 = (idx & 31) << 2;
        if (r < rows_valid) {
            float4 re = *(float4*)(sCre + r * LDC + c4);
            float4 im = *(float4*)(sCim + r * LDC + c4);
            float4 gx4 = *(const float4*)(g_gx + (row0 + r) * 128 + c4);
            float4 gy4 = *(const float4*)(g_gy + (row0 + r) * 128 + c4);
            float4 o;
            o.x = tanhf(gx4.x * re.x + gy4.x * im.x);
            o.y = tanhf(gx4.y * re.y + gy4.y * im.y);
            o.z = tanhf(gx4.z * re.z + gy4.z * im.z);
            o.w = tanhf(gx4.w * re.w + gy4.w * im.w);
            *(float4*)(g_xgf + (row0 + r) * 128 + c4) = o;
        }
    }
}

// ---------------------------------------------------------------------------
// 6) mlp0 (WMMA): h = relu([x_in|xdiff|xgf] @ W0 + b0)
// ---------------------------------------------------------------------------
__global__ __launch_bounds__(256) void g_mlp0(const float* __restrict__ x_in,
                                              const float* __restrict__ W0,
                                              const float* __restrict__ b0) {
    extern __shared__ __align__(16) char sm[];
    float* sA = (float*)sm;
    float* sB = (float*)(sm + SM_A);
    float* sC = (float*)sm;
    const int tid = threadIdx.x, wid = tid >> 5;
    const int wm = wid & 3, wn = wid >> 2;
    const size_t row0 = (size_t)blockIdx.x * 128;
    const int rows_valid = (int)min((size_t)128, (size_t)BV - row0);

    FragC cf[2][4];
#pragma unroll
    for (int i = 0; i < 2; i++)
#pragma unroll
        for (int j = 0; j < 4; j++) wmma::fill_fragment(cf[i][j], 0.f);

    for (int ck = 0; ck < 12; ck++) {
        const float* Ab = (ck < 4) ? x_in : (ck < 8) ? g_xdiff : g_xgf;
        __syncthreads();
        ldA(sA, Ab + row0 * 128 + (ck & 3) * 32, 128, rows_valid, tid);
        ldB(sB, W0 + (size_t)ck * 32 * 128, 128, tid);
        __syncthreads();
#pragma unroll
        for (int kk = 0; kk < 4; kk++) {
            FragA af[2];
            FragB bf[4];
#pragma unroll
            for (int i = 0; i < 2; i++)
                wmma::load_matrix_sync(af[i], sA + (wm * 32 + i * 16) * LDA + kk * 8, LDA);
#pragma unroll
            for (int j = 0; j < 4; j++)
                wmma::load_matrix_sync(bf[j], sB + kk * 8 * LDB + wn * 64 + j * 16, LDB);
#pragma unroll
            for (int i = 0; i < 2; i++)
#pragma unroll
                for (int j = 0; j < 4; j++)
                    wmma::mma_sync(cf[i][j], af[i], bf[j], cf[i][j]);
        }
    }
    __syncthreads();
#pragma unroll
    for (int i = 0; i < 2; i++)
#pragma unroll
        for (int j = 0; j < 4; j++)
            wmma::store_matrix_sync(sC + (wm * 32 + i * 16) * LDC + wn * 64 + j * 16,
                                    cf[i][j], LDC, wmma::mem_row_major);
    __syncthreads();
#pragma unroll
    for (int it = 0; it < 16; it++) {
        int idx = tid + it * 256;
        int r = idx >> 5, c4 = (idx & 31) << 2;
        if (r < rows_valid) {
            float4 v = *(float4*)(sC + r * LDC + c4);
            float4 bb = *(const float4*)(b0 + c4);
            float4 o;
            o.x = fmaxf(v.x + bb.x, 0.f);
            o.y = fmaxf(v.y + bb.y, 0.f);
            o.z = fmaxf(v.z + bb.z, 0.f);
            o.w = fmaxf(v.w + bb.w, 0.f);
            *(float4*)(g_h + (row0 + r) * 128 + c4) = o;
        }
    }
}

// ---------------------------------------------------------------------------
// 7) mlp1 (WMMA) + residual: out = h @ W1 + b1 + x_in
// ---------------------------------------------------------------------------
__global__ __launch_bounds__(256) void g_mlp1(const float* __restrict__ x_in,
                                              const float* __restrict__ W1,
                                              const float* __restrict__ b1,
                                              float* __restrict__ out) {
    extern __shared__ __align__(16) char sm[];
    float* sA = (float*)sm;
    float* sB = (float*)(sm + SM_A);
    float* sC = (float*)sm;
    const int tid = threadIdx.x, wid = tid >> 5;
    const int wm = wid & 3, wn = wid >> 2;
    const size_t row0 = (size_t)blockIdx.x * 128;
    const int rows_valid = (int)min((size_t)128, (size_t)BV - row0);

    FragC cf[2][4];
#pragma unroll
    for (int i = 0; i < 2; i++)
#pragma unroll
        for (int j = 0; j < 4; j++) wmma::fill_fragment(cf[i][j], 0.f);

#pragma unroll
    for (int ck = 0; ck < 4; ck++) {
        __syncthreads();
        ldA(sA, g_h + row0 * 128 + ck * 32, 128, rows_valid, tid);
        ldB(sB, W1 + (size_t)ck * 32 * 128, 128, tid);
        __syncthreads();
#pragma unroll
        for (int kk = 0; kk < 4; kk++) {
            FragA af[2];
            FragB bf[4];
#pragma unroll
            for (int i = 0; i < 2; i++)
                wmma::load_matrix_sync(af[i], sA + (wm * 32 + i * 16) * LDA + kk * 8, LDA);
#pragma unroll
            for (int j = 0; j < 4; j++)
                wmma::load_matrix_sync(bf[j], sB + kk * 8 * LDB + wn * 64 + j * 16, LDB);
#pragma unroll
            for (int i = 0; i < 2; i++)
#pragma unroll
                for (int j = 0; j < 4; j++)
                    wmma::mma_sync(cf[i][j], af[i], bf[j], cf[i][j]);
        }
    }
    __syncthreads();
#pragma unroll
    for (int i = 0; i < 2; i++)
#pragma unroll
        for (int j = 0; j < 4; j++)
            wmma::store_matrix_sync(sC + (wm * 32 + i * 16) * LDC + wn * 64 + j * 16,
                                    cf[i][j], LDC, wmma::mem_row_major);
    __syncthreads();
#pragma unroll
    for (int it = 0; it < 16; it++) {
        int idx = tid + it * 256;
        int r = idx >> 5, c4 = (idx & 31) << 2;
        if (r < rows_valid) {
            float4 v = *(float4*)(sC + r * LDC + c4);
            float4 bb = *(const float4*)(b1 + c4);
            float4 xi = *(const float4*)(x_in + (row0 + r) * 128 + c4);
            *(float4*)(out + (row0 + r) * 128 + c4) =
                make_float4(v.x + bb.x + xi.x, v.y + bb.y + xi.y,
                            v.z + bb.z + xi.z, v.w + bb.w + xi.w);
        }
    }
}

// ---------------------------------------------------------------------------
// Launch
// ---------------------------------------------------------------------------
extern "C" void kernel_launch(void* const* d_in, const int* in_sizes, int n_in,
                              void* d_out, int out_size) {
    const float* x_in  = (const float*)d_in[0];
    const float* mass  = (const float*)d_in[1];
    const float* evals = (const float*)d_in[3];
    const float* evecs = (const float*)d_in[4];
    const int*   grows = (const int*)d_in[5];
    const int*   gcols = (const int*)d_in[6];
    const float* gxv   = (const float*)d_in[7];
    const float* gyv   = (const float*)d_in[8];
    const float* dt    = (const float*)d_in[9];
    const float* A_re  = (const float*)d_in[10];
    const float* A_im  = (const float*)d_in[11];
    const float* W0    = (const float*)d_in[12];
    const float* b0    = (const float*)d_in[13];
    const float* W1    = (const float*)d_in[14];
    const float* b1    = (const float*)d_in[15];
    float* out = (float*)d_out;

    cudaFuncSetAttribute(k_project,  cudaFuncAttributeMaxDynamicSharedMemorySize, SMEM_NORM);
    cudaFuncSetAttribute(g_diffuse,  cudaFuncAttributeMaxDynamicSharedMemorySize, SMEM_NORM);
    cudaFuncSetAttribute(g_gradfeat, cudaFuncAttributeMaxDynamicSharedMemorySize, SMEM_GRAD);
    cudaFuncSetAttribute(g_mlp0,     cudaFuncAttributeMaxDynamicSharedMemorySize, SMEM_NORM);
    cudaFuncSetAttribute(g_mlp1,     cudaFuncAttributeMaxDynamicSharedMemorySize, SMEM_NORM);

    // CSR build (independent)
    k_zero_cnt<<<(BV + 255) / 256, 256>>>();
    k_hist<<<(BE + 255) / 256, 256>>>(grows);
    k_scanA<<<NSCAN, 512>>>();
    k_scanB<<<1, 512>>>();
    k_scanC<<<NSCAN, 512>>>();
    k_scatter<<<(BE + 255) / 256, 256>>>(grows, gcols, gxv, gyv);

    // spectral diffusion
    k_zero_spec<<<(Bn * Kn * Cn + 255) / 256, 256>>>();
    k_project<<<dim3(GRIDP, Bn), 256, SMEM_NORM>>>(x_in, mass, evecs);
    k_decay<<<(Bn * Kn * Cn + 255) / 256, 256>>>(evals, dt);
    g_diffuse<<<dim3(GRIDV, Bn), 256, SMEM_NORM>>>(evecs);

    // sparse gradients
    k_gather<<<BV, 128>>>();

    // gradient features + MLP
    g_gradfeat<<<GRIDM, 256, SMEM_GRAD>>>(A_re, A_im);
    g_mlp0<<<GRIDM, 256, SMEM_NORM>>>(x_in, W0, b0);
    g_mlp1<<<GRIDM, 256, SMEM_NORM>>>(x_in, W1, b1, out);
}

// round 5
// speedup vs baseline: 2.3208x; 1.2518x over previous
#include <cuda_runtime.h>
#include <cuda_pipeline.h>
#include <mma.h>
#include <math.h>
#include <stdint.h>

using namespace nvcuda;

#define Bn 4
#define Vn 50000
#define Cn 128
#define Kn 128
#define En 400000
#define BV (Bn * Vn)      // 200000
#define BE (Bn * En)      // 1600000
#define NSCAN 391
#define GRIDM 1563        // ceil(BV/128)
#define GRIDV 391         // ceil(Vn/128)
#define PROJ_VT 1024
#define GRIDP 49          // ceil(Vn/PROJ_VT)

// smem strides (floats)
#define LDA 36
#define LDB 136
#define LDE 132
#define LDC 132
#define ABUF (128 * LDA)   // 4608 floats
#define BBUF (32 * LDB)    // 4352 floats
#define SMEM_NORM (17920 * 4)    // 2*ABUF + 2*BBUF = 71680 B (epilogue sC fits inside)
#define SMEM_GRAD (35840 * 4)    // 4*ABUF + 4*BBUF = 143360 B
#define SM_E (32 * LDE * 4)
#define SMEM_PROJ (128 * LDC * 4)   // 67584 B

typedef wmma::fragment<wmma::matrix_a, 16, 16, 8, wmma::precision::tf32, wmma::row_major> FragA;
typedef wmma::fragment<wmma::matrix_a, 16, 16, 8, wmma::precision::tf32, wmma::col_major> FragAT;
typedef wmma::fragment<wmma::matrix_b, 16, 16, 8, wmma::precision::tf32, wmma::row_major> FragB;
typedef wmma::fragment<wmma::accumulator, 16, 16, 8, float> FragC;

// ---------------------------------------------------------------------------
// Scratch
// ---------------------------------------------------------------------------
__device__ __align__(16) float g_xspec[Bn * Kn * Cn];
__device__ __align__(16) float g_xdiff[(size_t)BV * Cn];
__device__ __align__(16) float g_gx[(size_t)BV * Cn];
__device__ __align__(16) float g_gy[(size_t)BV * Cn];
__device__ __align__(16) float g_xgf[(size_t)BV * Cn];
__device__ __align__(16) float g_h[(size_t)BV * Cn];

__device__ int   g_cnt[BV];
__device__ int   g_off[BV];
__device__ int   g_cur[BV];
__device__ int   g_bsum[NSCAN];
__device__ int   g_scol[BE];
__device__ float g_svx[BE];
__device__ float g_svy[BE];

// ---------------------------------------------------------------------------
// helpers
// ---------------------------------------------------------------------------
__device__ __forceinline__ float to_tf32(float x) { return wmma::__float_to_tf32(x); }

__device__ __forceinline__ void cpA(float* sA, const float* __restrict__ g,
                                    int ld, int rows_valid, int tid) {
#pragma unroll
    for (int it = 0; it < 4; it++) {
        int idx = tid + it * 256;
        int r = idx >> 3, c4 = (idx & 7) << 2;
        if (r < rows_valid)
            __pipeline_memcpy_async(sA + r * LDA + c4, g + (size_t)r * ld + c4, 16);
    }
}
__device__ __forceinline__ void cpB(float* sB, const float* __restrict__ g,
                                    int ld, int tid) {
#pragma unroll
    for (int it = 0; it < 4; it++) {
        int idx = tid + it * 256;
        int r = idx >> 5, c4 = (idx & 31) << 2;
        __pipeline_memcpy_async(sB + r * LDB + c4, g + (size_t)r * ld + c4, 16);
    }
}
__device__ __forceinline__ void zeroA2(float* sA0, float* sA1, int tid) {
#pragma unroll
    for (int it = 0; it < 9; it++) {
        int idx = (tid + it * 256) * 4;
        if (idx < ABUF) {
            *(float4*)(sA0 + idx) = make_float4(0.f, 0.f, 0.f, 0.f);
            *(float4*)(sA1 + idx) = make_float4(0.f, 0.f, 0.f, 0.f);
        }
    }
}
template<typename F>
__device__ __forceinline__ void cvt_frag(F& f) {
#pragma unroll
    for (int e = 0; e < f.num_elements; e++) f.x[e] = to_tf32(f.x[e]);
}

// ---------------------------------------------------------------------------
// zero kernels
// ---------------------------------------------------------------------------
__global__ void k_zero_spec() {
    int i = blockIdx.x * blockDim.x + threadIdx.x;
    if (i < Bn * Kn * Cn) g_xspec[i] = 0.f;
}
__global__ void k_zero_cnt() {
    int i = blockIdx.x * blockDim.x + threadIdx.x;
    if (i < BV) g_cnt[i] = 0;
}

// ---------------------------------------------------------------------------
// 1) projection (WMMA tf32)
// ---------------------------------------------------------------------------
__global__ __launch_bounds__(256) void k_project(const float* __restrict__ x_in,
                                                 const float* __restrict__ mass,
                                                 const float* __restrict__ evecs) {
    extern __shared__ __align__(16) char sm[];
    float* sE = (float*)sm;
    float* sX = (float*)(sm + SM_E);
    float* sC = (float*)sm;
    const int tid = threadIdx.x, wid = tid >> 5;
    const int wm = wid & 3, wn = wid >> 2;
    const int b = blockIdx.y;
    const int v0 = blockIdx.x * PROJ_VT;
    const int vend = min(v0 + PROJ_VT, Vn);

    FragC cf[2][4];
#pragma unroll
    for (int i = 0; i < 2; i++)
#pragma unroll
        for (int j = 0; j < 4; j++) wmma::fill_fragment(cf[i][j], 0.f);

    for (int vc = v0; vc < vend; vc += 32) {
        __syncthreads();
#pragma unroll
        for (int it = 0; it < 4; it++) {
            int idx = tid + it * 256;
            int r = idx >> 5, c4 = (idx & 31) << 2;
            int v = vc + r;
            float4 e4 = make_float4(0.f, 0.f, 0.f, 0.f);
            float4 x4 = make_float4(0.f, 0.f, 0.f, 0.f);
            if (v < Vn) {
                size_t base = ((size_t)b * Vn + v) * 128 + c4;
                e4 = *(const float4*)(evecs + base);
                float m = mass[b * Vn + v];
                x4 = *(const float4*)(x_in + base);
                x4.x *= m; x4.y *= m; x4.z *= m; x4.w *= m;
            }
            *(float4*)(sE + r * LDE + c4) =
                make_float4(to_tf32(e4.x), to_tf32(e4.y), to_tf32(e4.z), to_tf32(e4.w));
            *(float4*)(sX + r * LDB + c4) =
                make_float4(to_tf32(x4.x), to_tf32(x4.y), to_tf32(x4.z), to_tf32(x4.w));
        }
        __syncthreads();
#pragma unroll
        for (int kk = 0; kk < 4; kk++) {
            FragAT af[2];
            FragB bf[4];
#pragma unroll
            for (int i = 0; i < 2; i++)
                wmma::load_matrix_sync(af[i], sE + kk * 8 * LDE + wm * 32 + i * 16, LDE);
#pragma unroll
            for (int j = 0; j < 4; j++)
                wmma::load_matrix_sync(bf[j], sX + kk * 8 * LDB + wn * 64 + j * 16, LDB);
#pragma unroll
            for (int i = 0; i < 2; i++)
#pragma unroll
                for (int j = 0; j < 4; j++)
                    wmma::mma_sync(cf[i][j], af[i], bf[j], cf[i][j]);
        }
    }
    __syncthreads();
#pragma unroll
    for (int i = 0; i < 2; i++)
#pragma unroll
        for (int j = 0; j < 4; j++)
            wmma::store_matrix_sync(sC + (wm * 32 + i * 16) * LDC + wn * 64 + j * 16,
                                    cf[i][j], LDC, wmma::mem_row_major);
    __syncthreads();
    float* dst = g_xspec + (size_t)b * 16384;
#pragma unroll
    for (int it = 0; it < 16; it++) {
        int idx = tid + it * 256;
        int r = idx >> 5, c4 = (idx & 31) << 2;
        float4 v = *(float4*)(sC + r * LDC + c4);
        atomicAdd(&dst[r * 128 + c4 + 0], v.x);
        atomicAdd(&dst[r * 128 + c4 + 1], v.y);
        atomicAdd(&dst[r * 128 + c4 + 2], v.z);
        atomicAdd(&dst[r * 128 + c4 + 3], v.w);
    }
}

// ---------------------------------------------------------------------------
// 2) decay
// ---------------------------------------------------------------------------
__global__ void k_decay(const float* __restrict__ evals, const float* __restrict__ dt) {
    int i = blockIdx.x * blockDim.x + threadIdx.x;
    if (i >= Bn * Kn * Cn) return;
    int c = i & 127, k = (i >> 7) & 127, b = i >> 14;
    float t = fmaxf(dt[c], 1e-8f);
    g_xspec[i] *= expf(-evals[b * 128 + k] * t);
}

// ---------------------------------------------------------------------------
// MMA helper: one 32-wide K chunk on a 128x128 tile
// ---------------------------------------------------------------------------
__device__ __forceinline__ void mma_chunk(const float* sA, const float* sB,
                                          FragC cf[2][4], int wm, int wn) {
#pragma unroll
    for (int kk = 0; kk < 4; kk++) {
        FragA af[2];
        FragB bf[4];
#pragma unroll
        for (int i = 0; i < 2; i++) {
            wmma::load_matrix_sync(af[i], sA + (wm * 32 + i * 16) * LDA + kk * 8, LDA);
            cvt_frag(af[i]);
        }
#pragma unroll
        for (int j = 0; j < 4; j++) {
            wmma::load_matrix_sync(bf[j], sB + kk * 8 * LDB + wn * 64 + j * 16, LDB);
            cvt_frag(bf[j]);
        }
#pragma unroll
        for (int i = 0; i < 2; i++)
#pragma unroll
            for (int j = 0; j < 4; j++)
                wmma::mma_sync(cf[i][j], af[i], bf[j], cf[i][j]);
    }
}

// ---------------------------------------------------------------------------
// 3) diffuse (cp.async double-buffered)
// ---------------------------------------------------------------------------
__global__ __launch_bounds__(256) void g_diffuse(const float* __restrict__ evecs) {
    extern __shared__ __align__(16) char sm[];
    float* sA[2] = {(float*)sm, (float*)sm + ABUF};
    float* sB[2] = {(float*)sm + 2 * ABUF, (float*)sm + 2 * ABUF + BBUF};
    float* sC = (float*)sm;
    const int tid = threadIdx.x, wid = tid >> 5;
    const int wm = wid & 3, wn = wid >> 2;
    const int b = blockIdx.y;
    const int row0 = blockIdx.x * 128;
    const int rows_valid = min(128, Vn - row0);
    const float* A = evecs + ((size_t)b * Vn + row0) * 128;
    const float* Bp = g_xspec + (size_t)b * 16384;

    FragC cf[2][4];
#pragma unroll
    for (int i = 0; i < 2; i++)
#pragma unroll
        for (int j = 0; j < 4; j++) wmma::fill_fragment(cf[i][j], 0.f);

    if (rows_valid < 128) { zeroA2(sA[0], sA[1], tid); __syncthreads(); }

    cpA(sA[0], A, 128, rows_valid, tid);
    cpB(sB[0], Bp, 128, tid);
    __pipeline_commit();
#pragma unroll
    for (int ck = 0; ck < 4; ck++) {
        if (ck + 1 < 4) {
            cpA(sA[(ck + 1) & 1], A + (ck + 1) * 32, 128, rows_valid, tid);
            cpB(sB[(ck + 1) & 1], Bp + (ck + 1) * 32 * 128, 128, tid);
            __pipeline_commit();
            __pipeline_wait_prior(1);
        } else {
            __pipeline_wait_prior(0);
        }
        __syncthreads();
        mma_chunk(sA[ck & 1], sB[ck & 1], cf, wm, wn);
        __syncthreads();
    }
#pragma unroll
    for (int i = 0; i < 2; i++)
#pragma unroll
        for (int j = 0; j < 4; j++)
            wmma::store_matrix_sync(sC + (wm * 32 + i * 16) * LDC + wn * 64 + j * 16,
                                    cf[i][j], LDC, wmma::mem_row_major);
    __syncthreads();
    float* outp = g_xdiff + ((size_t)b * Vn + row0) * 128;
#pragma unroll
    for (int it = 0; it < 16; it++) {
        int idx = tid + it * 256;
        int r = idx >> 5, c4 = (idx & 31) << 2;
        if (r < rows_valid)
            *(float4*)(outp + (size_t)r * 128 + c4) = *(float4*)(sC + r * LDC + c4);
    }
}

// ---------------------------------------------------------------------------
// 4) CSR build + gather
// ---------------------------------------------------------------------------
__global__ __launch_bounds__(256) void k_hist(const int* __restrict__ rows) {
    int be = blockIdx.x * blockDim.x + threadIdx.x;
    if (be >= BE) return;
    int b = be / En;
    atomicAdd(&g_cnt[b * Vn + rows[be]], 1);
}
__global__ __launch_bounds__(512) void k_scanA() {
    __shared__ int s[512];
    int t = threadIdx.x;
    int i = blockIdx.x * 512 + t;
    int v = (i < BV) ? g_cnt[i] : 0;
    s[t] = v;
    __syncthreads();
#pragma unroll
    for (int d = 1; d < 512; d <<= 1) {
        int x = (t >= d) ? s[t - d] : 0;
        __syncthreads(); s[t] += x; __syncthreads();
    }
    if (i < BV) g_off[i] = s[t] - v;
    if (t == 511) g_bsum[blockIdx.x] = s[511];
}
__global__ __launch_bounds__(512) void k_scanB() {
    __shared__ int s[512];
    int t = threadIdx.x;
    int v = (t < NSCAN) ? g_bsum[t] : 0;
    s[t] = v;
    __syncthreads();
#pragma unroll
    for (int d = 1; d < 512; d <<= 1) {
        int x = (t >= d) ? s[t - d] : 0;
        __syncthreads(); s[t] += x; __syncthreads();
    }
    if (t < NSCAN) g_bsum[t] = s[t] - v;
}
__global__ __launch_bounds__(512) void k_scanC() {
    int i = blockIdx.x * 512 + threadIdx.x;
    if (i >= BV) return;
    int o = g_off[i] + g_bsum[blockIdx.x];
    g_off[i] = o;
    g_cur[i] = o;
}
__global__ __launch_bounds__(256) void k_scatter(const int* __restrict__ rows,
                                                 const int* __restrict__ cols,
                                                 const float* __restrict__ xv,
                                                 const float* __restrict__ yv) {
    int be = blockIdx.x * blockDim.x + threadIdx.x;
    if (be >= BE) return;
    int b = be / En;
    int pos = atomicAdd(&g_cur[b * Vn + rows[be]], 1);
    g_scol[pos] = cols[be];
    g_svx[pos] = xv[be];
    g_svy[pos] = yv[be];
}
// warp per row, float4 lanes
__global__ __launch_bounds__(128) void k_gather() {
    const int w = threadIdx.x >> 5;
    const int lane = threadIdx.x & 31;
    const int flat = blockIdx.x * 4 + w;
    const int b = flat / Vn;
    const int start = g_off[flat];
    const int n = g_cnt[flat];
    const float4* __restrict__ xb = (const float4*)(g_xdiff + (size_t)b * Vn * 128);

    float4 ax = make_float4(0.f, 0.f, 0.f, 0.f);
    float4 ay = make_float4(0.f, 0.f, 0.f, 0.f);
    int col = 0; float vx = 0.f, vy = 0.f;
    if (n > 0) { col = g_scol[start]; vx = g_svx[start]; vy = g_svy[start]; }
    for (int e = 0; e < n; e++) {
        int coln = 0; float vxn = 0.f, vyn = 0.f;
        if (e + 1 < n) {
            coln = g_scol[start + e + 1];
            vxn = g_svx[start + e + 1];
            vyn = g_svy[start + e + 1];
        }
        float4 x = xb[(size_t)col * 32 + lane];
        ax.x = fmaf(vx, x.x, ax.x); ax.y = fmaf(vx, x.y, ax.y);
        ax.z = fmaf(vx, x.z, ax.z); ax.w = fmaf(vx, x.w, ax.w);
        ay.x = fmaf(vy, x.x, ay.x); ay.y = fmaf(vy, x.y, ay.y);
        ay.z = fmaf(vy, x.z, ay.z); ay.w = fmaf(vy, x.w, ay.w);
        col = coln; vx = vxn; vy = vyn;
    }
    *(float4*)(g_gx + (size_t)flat * 128 + lane * 4) = ax;
    *(float4*)(g_gy + (size_t)flat * 128 + lane * 4) = ay;
}

// ---------------------------------------------------------------------------
// 5) gradfeat (cp.async double-buffered dual GEMM)
// ---------------------------------------------------------------------------
__global__ __launch_bounds__(256) void g_gradfeat(const float* __restrict__ A_re,
                                                  const float* __restrict__ A_im) {
    extern __shared__ __align__(16) char sm[];
    float* base = (float*)sm;
    float* sGx[2] = {base, base + ABUF};
    float* sGy[2] = {base + 2 * ABUF, base + 3 * ABUF};
    float* sRe[2] = {base + 4 * ABUF, base + 4 * ABUF + BBUF};
    float* sIm[2] = {base + 4 * ABUF + 2 * BBUF, base + 4 * ABUF + 3 * BBUF};
    float* sCre = base;
    float* sCim = base + 128 * LDC;
    const int tid = threadIdx.x, wid = tid >> 5;
    const int wm = wid & 3, wn = wid >> 2;
    const size_t row0 = (size_t)blockIdx.x * 128;
    const int rows_valid = (int)min((size_t)128, (size_t)BV - row0);

    FragC cre[2][4], cim[2][4];
#pragma unroll
    for (int i = 0; i < 2; i++)
#pragma unroll
        for (int j = 0; j < 4; j++) {
            wmma::fill_fragment(cre[i][j], 0.f);
            wmma::fill_fragment(cim[i][j], 0.f);
        }

    if (rows_valid < 128) {
        zeroA2(sGx[0], sGx[1], tid);
        zeroA2(sGy[0], sGy[1], tid);
        __syncthreads();
    }

    cpA(sGx[0], g_gx + row0 * 128, 128, rows_valid, tid);
    cpA(sGy[0], g_gy + row0 * 128, 128, rows_valid, tid);
    cpB(sRe[0], A_re, 128, tid);
    cpB(sIm[0], A_im, 128, tid);
    __pipeline_commit();
#pragma unroll
    for (int ck = 0; ck < 4; ck++) {
        if (ck + 1 < 4) {
            int nb = (ck + 1) & 1;
            cpA(sGx[nb], g_gx + row0 * 128 + (ck + 1) * 32, 128, rows_valid, tid);
            cpA(sGy[nb], g_gy + row0 * 128 + (ck + 1) * 32, 128, rows_valid, tid);
            cpB(sRe[nb], A_re + (ck + 1) * 32 * 128, 128, tid);
            cpB(sIm[nb], A_im + (ck + 1) * 32 * 128, 128, tid);
            __pipeline_commit();
            __pipeline_wait_prior(1);
        } else {
            __pipeline_wait_prior(0);
        }
        __syncthreads();
        const int cb = ck & 1;
#pragma unroll
        for (int kk = 0; kk < 4; kk++) {
            FragA agx[2], agy[2], agyn[2];
            FragB bre[4], bim[4];
#pragma unroll
            for (int i = 0; i < 2; i++) {
                wmma::load_matrix_sync(agx[i], sGx[cb] + (wm * 32 + i * 16) * LDA + kk * 8, LDA);
                wmma::load_matrix_sync(agy[i], sGy[cb] + (wm * 32 + i * 16) * LDA + kk * 8, LDA);
                cvt_frag(agx[i]);
                cvt_frag(agy[i]);
#pragma unroll
                for (int e = 0; e < agy[i].num_elements; e++) agyn[i].x[e] = -agy[i].x[e];
            }
#pragma unroll
            for (int j = 0; j < 4; j++) {
                wmma::load_matrix_sync(bre[j], sRe[cb] + kk * 8 * LDB + wn * 64 + j * 16, LDB);
                wmma::load_matrix_sync(bim[j], sIm[cb] + kk * 8 * LDB + wn * 64 + j * 16, LDB);
                cvt_frag(bre[j]);
                cvt_frag(bim[j]);
            }
#pragma unroll
            for (int i = 0; i < 2; i++)
#pragma unroll
                for (int j = 0; j < 4; j++) {
                    wmma::mma_sync(cre[i][j], agx[i],  bre[j], cre[i][j]);
                    wmma::mma_sync(cre[i][j], agyn[i], bim[j], cre[i][j]);
                    wmma::mma_sync(cim[i][j], agy[i],  bre[j], cim[i][j]);
                    wmma::mma_sync(cim[i][j], agx[i],  bim[j], cim[i][j]);
                }
        }
        __syncthreads();
    }
#pragma unroll
    for (int i = 0; i < 2; i++)
#pragma unroll
        for (int j = 0; j < 4; j++) {
            wmma::store_matrix_sync(sCre + (wm * 32 + i * 16) * LDC + wn * 64 + j * 16,
                                    cre[i][j], LDC, wmma::mem_row_major);
            wmma::store_matrix_sync(sCim + (wm * 32 + i * 16) * LDC + wn * 64 + j * 16,
                                    cim[i][j], LDC, wmma::mem_row_major);
        }
    __syncthreads();
#pragma unroll
    for (int it = 0; it < 16; it++) {
        int idx = tid + it * 256;
        int r = idx >> 5, c4 = (idx & 31) << 2;
        if (r < rows_valid) {
            float4 re = *(float4*)(sCre + r * LDC + c4);
            float4 im = *(float4*)(sCim + r * LDC + c4);
            float4 gx4 = *(const float4*)(g_gx + (row0 + r) * 128 + c4);
            float4 gy4 = *(const float4*)(g_gy + (row0 + r) * 128 + c4);
            float4 o;
            o.x = tanhf(gx4.x * re.x + gy4.x * im.x);
            o.y = tanhf(gx4.y * re.y + gy4.y * im.y);
            o.z = tanhf(gx4.z * re.z + gy4.z * im.z);
            o.w = tanhf(gx4.w * re.w + gy4.w * im.w);
            *(float4*)(g_xgf + (row0 + r) * 128 + c4) = o;
        }
    }
}

// ---------------------------------------------------------------------------
// 6) mlp0 (cp.async): h = relu([x_in|xdiff|xgf] @ W0 + b0)
// ---------------------------------------------------------------------------
__global__ __launch_bounds__(256) void g_mlp0(const float* __restrict__ x_in,
                                              const float* __restrict__ W0,
                                              const float* __restrict__ b0) {
    extern __shared__ __align__(16) char sm[];
    float* sA[2] = {(float*)sm, (float*)sm + ABUF};
    float* sB[2] = {(float*)sm + 2 * ABUF, (float*)sm + 2 * ABUF + BBUF};
    float* sC = (float*)sm;
    const int tid = threadIdx.x, wid = tid >> 5;
    const int wm = wid & 3, wn = wid >> 2;
    const size_t row0 = (size_t)blockIdx.x * 128;
    const int rows_valid = (int)min((size_t)128, (size_t)BV - row0);

    FragC cf[2][4];
#pragma unroll
    for (int i = 0; i < 2; i++)
#pragma unroll
        for (int j = 0; j < 4; j++) wmma::fill_fragment(cf[i][j], 0.f);

    if (rows_valid < 128) { zeroA2(sA[0], sA[1], tid); __syncthreads(); }

    const float* bases[3] = {x_in + row0 * 128, g_xdiff + row0 * 128, g_xgf + row0 * 128};

    cpA(sA[0], bases[0], 128, rows_valid, tid);
    cpB(sB[0], W0, 128, tid);
    __pipeline_commit();
    for (int ck = 0; ck < 12; ck++) {
        if (ck + 1 < 12) {
            int nc = ck + 1;
            cpA(sA[nc & 1], bases[nc >> 2] + (nc & 3) * 32, 128, rows_valid, tid);
            cpB(sB[nc & 1], W0 + (size_t)nc * 32 * 128, 128, tid);
            __pipeline_commit();
            __pipeline_wait_prior(1);
        } else {
            __pipeline_wait_prior(0);
        }
        __syncthreads();
        mma_chunk(sA[ck & 1], sB[ck & 1], cf, wm, wn);
        __syncthreads();
    }
#pragma unroll
    for (int i = 0; i < 2; i++)
#pragma unroll
        for (int j = 0; j < 4; j++)
            wmma::store_matrix_sync(sC + (wm * 32 + i * 16) * LDC + wn * 64 + j * 16,
                                    cf[i][j], LDC, wmma::mem_row_major);
    __syncthreads();
#pragma unroll
    for (int it = 0; it < 16; it++) {
        int idx = tid + it * 256;
        int r = idx >> 5, c4 = (idx & 31) << 2;
        if (r < rows_valid) {
            float4 v = *(float4*)(sC + r * LDC + c4);
            float4 bb = *(const float4*)(b0 + c4);
            float4 o;
            o.x = fmaxf(v.x + bb.x, 0.f);
            o.y = fmaxf(v.y + bb.y, 0.f);
            o.z = fmaxf(v.z + bb.z, 0.f);
            o.w = fmaxf(v.w + bb.w, 0.f);
            *(float4*)(g_h + (row0 + r) * 128 + c4) = o;
        }
    }
}

// ---------------------------------------------------------------------------
// 7) mlp1 (cp.async) + residual
// ---------------------------------------------------------------------------
__global__ __launch_bounds__(256) void g_mlp1(const float* __restrict__ x_in,
                                              const float* __restrict__ W1,
                                              const float* __restrict__ b1,
                                              float* __restrict__ out) {
    extern __shared__ __align__(16) char sm[];
    float* sA[2] = {(float*)sm, (float*)sm + ABUF};
    float* sB[2] = {(float*)sm + 2 * ABUF, (float*)sm + 2 * ABUF + BBUF};
    float* sC = (float*)sm;
    const int tid = threadIdx.x, wid = tid >> 5;
    const int wm = wid & 3, wn = wid >> 2;
    const size_t row0 = (size_t)blockIdx.x * 128;
    const int rows_valid = (int)min((size_t)128, (size_t)BV - row0);

    FragC cf[2][4];
#pragma unroll
    for (int i = 0; i < 2; i++)
#pragma unroll
        for (int j = 0; j < 4; j++) wmma::fill_fragment(cf[i][j], 0.f);

    if (rows_valid < 128) { zeroA2(sA[0], sA[1], tid); __syncthreads(); }

    cpA(sA[0], g_h + row0 * 128, 128, rows_valid, tid);
    cpB(sB[0], W1, 128, tid);
    __pipeline_commit();
#pragma unroll
    for (int ck = 0; ck < 4; ck++) {
        if (ck + 1 < 4) {
            cpA(sA[(ck + 1) & 1], g_h + row0 * 128 + (ck + 1) * 32, 128, rows_valid, tid);
            cpB(sB[(ck + 1) & 1], W1 + (size_t)(ck + 1) * 32 * 128, 128, tid);
            __pipeline_commit();
            __pipeline_wait_prior(1);
        } else {
            __pipeline_wait_prior(0);
        }
        __syncthreads();
        mma_chunk(sA[ck & 1], sB[ck & 1], cf, wm, wn);
        __syncthreads();
    }
#pragma unroll
    for (int i = 0; i < 2; i++)
#pragma unroll
        for (int j = 0; j < 4; j++)
            wmma::store_matrix_sync(sC + (wm * 32 + i * 16) * LDC + wn * 64 + j * 16,
                                    cf[i][j], LDC, wmma::mem_row_major);
    __syncthreads();
#pragma unroll
    for (int it = 0; it < 16; it++) {
        int idx = tid + it * 256;
        int r = idx >> 5, c4 = (idx & 31) << 2;
        if (r < rows_valid) {
            float4 v = *(float4*)(sC + r * LDC + c4);
            float4 bb = *(const float4*)(b1 + c4);
            float4 xi = *(const float4*)(x_in + (row0 + r) * 128 + c4);
            *(float4*)(out + (row0 + r) * 128 + c4) =
                make_float4(v.x + bb.x + xi.x, v.y + bb.y + xi.y,
                            v.z + bb.z + xi.z, v.w + bb.w + xi.w);
        }
    }
}

// ---------------------------------------------------------------------------
// Launch
// ---------------------------------------------------------------------------
extern "C" void kernel_launch(void* const* d_in, const int* in_sizes, int n_in,
                              void* d_out, int out_size) {
    const float* x_in  = (const float*)d_in[0];
    const float* mass  = (const float*)d_in[1];
    const float* evals = (const float*)d_in[3];
    const float* evecs = (const float*)d_in[4];
    const int*   grows = (const int*)d_in[5];
    const int*   gcols = (const int*)d_in[6];
    const float* gxv   = (const float*)d_in[7];
    const float* gyv   = (const float*)d_in[8];
    const float* dt    = (const float*)d_in[9];
    const float* A_re  = (const float*)d_in[10];
    const float* A_im  = (const float*)d_in[11];
    const float* W0    = (const float*)d_in[12];
    const float* b0    = (const float*)d_in[13];
    const float* W1    = (const float*)d_in[14];
    const float* b1    = (const float*)d_in[15];
    float* out = (float*)d_out;

    cudaFuncSetAttribute(k_project,  cudaFuncAttributeMaxDynamicSharedMemorySize, SMEM_PROJ);
    cudaFuncSetAttribute(g_diffuse,  cudaFuncAttributeMaxDynamicSharedMemorySize, SMEM_NORM);
    cudaFuncSetAttribute(g_gradfeat, cudaFuncAttributeMaxDynamicSharedMemorySize, SMEM_GRAD);
    cudaFuncSetAttribute(g_mlp0,     cudaFuncAttributeMaxDynamicSharedMemorySize, SMEM_NORM);
    cudaFuncSetAttribute(g_mlp1,     cudaFuncAttributeMaxDynamicSharedMemorySize, SMEM_NORM);

    // CSR build (independent)
    k_zero_cnt<<<(BV + 255) / 256, 256>>>();
    k_hist<<<(BE + 255) / 256, 256>>>(grows);
    k_scanA<<<NSCAN, 512>>>();
    k_scanB<<<1, 512>>>();
    k_scanC<<<NSCAN, 512>>>();
    k_scatter<<<(BE + 255) / 256, 256>>>(grows, gcols, gxv, gyv);

    // spectral diffusion
    k_zero_spec<<<(Bn * Kn * Cn + 255) / 256, 256>>>();
    k_project<<<dim3(GRIDP, Bn), 256, SMEM_PROJ>>>(x_in, mass, evecs);
    k_decay<<<(Bn * Kn * Cn + 255) / 256, 256>>>(evals, dt);
    g_diffuse<<<dim3(GRIDV, Bn), 256, SMEM_NORM>>>(evecs);

    // sparse gradients
    k_gather<<<BV / 4, 128>>>();

    // gradient features + MLP
    g_gradfeat<<<GRIDM, 256, SMEM_GRAD>>>(A_re, A_im);
    g_mlp0<<<GRIDM, 256, SMEM_NORM>>>(x_in, W0, b0);
    g_mlp1<<<GRIDM, 256, SMEM_NORM>>>(x_in, W1, b1, out);
}

// round 6
// speedup vs baseline: 2.4152x; 1.0407x over previous
#include <cuda_runtime.h>
#include <cuda_pipeline.h>
#include <mma.h>
#include <math.h>
#include <stdint.h>

using namespace nvcuda;

#define Bn 4
#define Vn 50000
#define Cn 128
#define Kn 128
#define En 400000
#define BV (Bn * Vn)      // 200000
#define BE (Bn * En)      // 1600000
#define NSCAN 391
#define GRIDM 1563        // ceil(BV/128)
#define GRIDV 391         // ceil(Vn/128)
#define PROJ_VT 1024
#define GRIDP 49          // ceil(Vn/PROJ_VT)

// smem strides (floats)
#define LDA 36
#define LDB 136
#define LDE 132
#define LDC 132
#define ABUF (128 * LDA)   // 4608 floats
#define BBUF (32 * LDB)    // 4352 floats
#define SMEM_NORM (17920 * 4)    // 2*ABUF + 2*BBUF = 71680 B
#define SMEM_GRAD (35840 * 4)    // 4*ABUF + 4*BBUF = 143360 B
#define SM_E (32 * LDE * 4)
#define SMEM_PROJ (128 * LDC * 4)   // 67584 B

typedef wmma::fragment<wmma::matrix_a, 16, 16, 8, wmma::precision::tf32, wmma::row_major> FragA;
typedef wmma::fragment<wmma::matrix_a, 16, 16, 8, wmma::precision::tf32, wmma::col_major> FragAT;
typedef wmma::fragment<wmma::matrix_b, 16, 16, 8, wmma::precision::tf32, wmma::row_major> FragB;
typedef wmma::fragment<wmma::accumulator, 16, 16, 8, float> FragC;

// ---------------------------------------------------------------------------
// Scratch
// ---------------------------------------------------------------------------
__device__ __align__(16) float g_xspec[Bn * Kn * Cn];
__device__ __align__(16) float g_xdiff[(size_t)BV * Cn];
__device__ __align__(16) float g_gx[(size_t)BV * Cn];
__device__ __align__(16) float g_gy[(size_t)BV * Cn];
__device__ __align__(16) float g_xgf[(size_t)BV * Cn];
__device__ __align__(16) float g_h[(size_t)BV * Cn];

__device__ int    g_cnt[BV];
__device__ int    g_off[BV];
__device__ int    g_cur[BV];
__device__ int    g_bsum[NSCAN];
__device__ __align__(16) float4 g_edge[BE];   // {col(bits), vx, vy, unused}

// ---------------------------------------------------------------------------
// helpers
// ---------------------------------------------------------------------------
__device__ __forceinline__ float to_tf32(float x) { return wmma::__float_to_tf32(x); }

template<int NT>
__device__ __forceinline__ void cpA(float* sA, const float* __restrict__ g,
                                    int ld, int rows_valid, int tid) {
#pragma unroll
    for (int it = 0; it < 1024 / NT; it++) {
        int idx = tid + it * NT;
        int r = idx >> 3, c4 = (idx & 7) << 2;
        if (r < rows_valid)
            __pipeline_memcpy_async(sA + r * LDA + c4, g + (size_t)r * ld + c4, 16);
    }
}
template<int NT>
__device__ __forceinline__ void cpB(float* sB, const float* __restrict__ g,
                                    int ld, int tid) {
#pragma unroll
    for (int it = 0; it < 1024 / NT; it++) {
        int idx = tid + it * NT;
        int r = idx >> 5, c4 = (idx & 31) << 2;
        __pipeline_memcpy_async(sB + r * LDB + c4, g + (size_t)r * ld + c4, 16);
    }
}
template<int NT>
__device__ __forceinline__ void zeroA2(float* sA0, float* sA1, int tid) {
#pragma unroll
    for (int it = 0; it < (ABUF / 4 + NT - 1) / NT; it++) {
        int idx = (tid + it * NT) * 4;
        if (idx < ABUF) {
            *(float4*)(sA0 + idx) = make_float4(0.f, 0.f, 0.f, 0.f);
            *(float4*)(sA1 + idx) = make_float4(0.f, 0.f, 0.f, 0.f);
        }
    }
}
template<typename F>
__device__ __forceinline__ void cvt_frag(F& f) {
#pragma unroll
    for (int e = 0; e < f.num_elements; e++) f.x[e] = to_tf32(f.x[e]);
}

// ---------------------------------------------------------------------------
// zero kernels
// ---------------------------------------------------------------------------
__global__ void k_zero_spec() {
    int i = blockIdx.x * blockDim.x + threadIdx.x;
    if (i < Bn * Kn * Cn) g_xspec[i] = 0.f;
}
__global__ void k_zero_cnt() {
    int i = blockIdx.x * blockDim.x + threadIdx.x;
    if (i < BV) g_cnt[i] = 0;
}

// ---------------------------------------------------------------------------
// 1) projection (WMMA tf32)
// ---------------------------------------------------------------------------
__global__ __launch_bounds__(256) void k_project(const float* __restrict__ x_in,
                                                 const float* __restrict__ mass,
                                                 const float* __restrict__ evecs) {
    extern __shared__ __align__(16) char sm[];
    float* sE = (float*)sm;
    float* sX = (float*)(sm + SM_E);
    float* sC = (float*)sm;
    const int tid = threadIdx.x, wid = tid >> 5;
    const int wm = wid & 3, wn = wid >> 2;
    const int b = blockIdx.y;
    const int v0 = blockIdx.x * PROJ_VT;
    const int vend = min(v0 + PROJ_VT, Vn);

    FragC cf[2][4];
#pragma unroll
    for (int i = 0; i < 2; i++)
#pragma unroll
        for (int j = 0; j < 4; j++) wmma::fill_fragment(cf[i][j], 0.f);

    for (int vc = v0; vc < vend; vc += 32) {
        __syncthreads();
#pragma unroll
        for (int it = 0; it < 4; it++) {
            int idx = tid + it * 256;
            int r = idx >> 5, c4 = (idx & 31) << 2;
            int v = vc + r;
            float4 e4 = make_float4(0.f, 0.f, 0.f, 0.f);
            float4 x4 = make_float4(0.f, 0.f, 0.f, 0.f);
            if (v < Vn) {
                size_t base = ((size_t)b * Vn + v) * 128 + c4;
                e4 = *(const float4*)(evecs + base);
                float m = mass[b * Vn + v];
                x4 = *(const float4*)(x_in + base);
                x4.x *= m; x4.y *= m; x4.z *= m; x4.w *= m;
            }
            *(float4*)(sE + r * LDE + c4) =
                make_float4(to_tf32(e4.x), to_tf32(e4.y), to_tf32(e4.z), to_tf32(e4.w));
            *(float4*)(sX + r * LDB + c4) =
                make_float4(to_tf32(x4.x), to_tf32(x4.y), to_tf32(x4.z), to_tf32(x4.w));
        }
        __syncthreads();
#pragma unroll
        for (int kk = 0; kk < 4; kk++) {
            FragAT af[2];
            FragB bf[4];
#pragma unroll
            for (int i = 0; i < 2; i++)
                wmma::load_matrix_sync(af[i], sE + kk * 8 * LDE + wm * 32 + i * 16, LDE);
#pragma unroll
            for (int j = 0; j < 4; j++)
                wmma::load_matrix_sync(bf[j], sX + kk * 8 * LDB + wn * 64 + j * 16, LDB);
#pragma unroll
            for (int i = 0; i < 2; i++)
#pragma unroll
                for (int j = 0; j < 4; j++)
                    wmma::mma_sync(cf[i][j], af[i], bf[j], cf[i][j]);
        }
    }
    __syncthreads();
#pragma unroll
    for (int i = 0; i < 2; i++)
#pragma unroll
        for (int j = 0; j < 4; j++)
            wmma::store_matrix_sync(sC + (wm * 32 + i * 16) * LDC + wn * 64 + j * 16,
                                    cf[i][j], LDC, wmma::mem_row_major);
    __syncthreads();
    float* dst = g_xspec + (size_t)b * 16384;
#pragma unroll
    for (int it = 0; it < 16; it++) {
        int idx = tid + it * 256;
        int r = idx >> 5, c4 = (idx & 31) << 2;
        float4 v = *(float4*)(sC + r * LDC + c4);
        atomicAdd(&dst[r * 128 + c4 + 0], v.x);
        atomicAdd(&dst[r * 128 + c4 + 1], v.y);
        atomicAdd(&dst[r * 128 + c4 + 2], v.z);
        atomicAdd(&dst[r * 128 + c4 + 3], v.w);
    }
}

// ---------------------------------------------------------------------------
// 2) decay
// ---------------------------------------------------------------------------
__global__ void k_decay(const float* __restrict__ evals, const float* __restrict__ dt) {
    int i = blockIdx.x * blockDim.x + threadIdx.x;
    if (i >= Bn * Kn * Cn) return;
    int c = i & 127, k = (i >> 7) & 127, b = i >> 14;
    float t = fmaxf(dt[c], 1e-8f);
    g_xspec[i] *= expf(-evals[b * 128 + k] * t);
}

// ---------------------------------------------------------------------------
// MMA helper: one 32-wide K chunk on a 128x128 tile (256-thread kernels)
// ---------------------------------------------------------------------------
__device__ __forceinline__ void mma_chunk(const float* sA, const float* sB,
                                          FragC cf[2][4], int wm, int wn) {
#pragma unroll
    for (int kk = 0; kk < 4; kk++) {
        FragA af[2];
        FragB bf[4];
#pragma unroll
        for (int i = 0; i < 2; i++) {
            wmma::load_matrix_sync(af[i], sA + (wm * 32 + i * 16) * LDA + kk * 8, LDA);
            cvt_frag(af[i]);
        }
#pragma unroll
        for (int j = 0; j < 4; j++) {
            wmma::load_matrix_sync(bf[j], sB + kk * 8 * LDB + wn * 64 + j * 16, LDB);
            cvt_frag(bf[j]);
        }
#pragma unroll
        for (int i = 0; i < 2; i++)
#pragma unroll
            for (int j = 0; j < 4; j++)
                wmma::mma_sync(cf[i][j], af[i], bf[j], cf[i][j]);
    }
}

// ---------------------------------------------------------------------------
// 3) diffuse (cp.async double-buffered)
// ---------------------------------------------------------------------------
__global__ __launch_bounds__(256) void g_diffuse(const float* __restrict__ evecs) {
    extern __shared__ __align__(16) char sm[];
    float* sA[2] = {(float*)sm, (float*)sm + ABUF};
    float* sB[2] = {(float*)sm + 2 * ABUF, (float*)sm + 2 * ABUF + BBUF};
    float* sC = (float*)sm;
    const int tid = threadIdx.x, wid = tid >> 5;
    const int wm = wid & 3, wn = wid >> 2;
    const int b = blockIdx.y;
    const int row0 = blockIdx.x * 128;
    const int rows_valid = min(128, Vn - row0);
    const float* A = evecs + ((size_t)b * Vn + row0) * 128;
    const float* Bp = g_xspec + (size_t)b * 16384;

    FragC cf[2][4];
#pragma unroll
    for (int i = 0; i < 2; i++)
#pragma unroll
        for (int j = 0; j < 4; j++) wmma::fill_fragment(cf[i][j], 0.f);

    if (rows_valid < 128) { zeroA2<256>(sA[0], sA[1], tid); __syncthreads(); }

    cpA<256>(sA[0], A, 128, rows_valid, tid);
    cpB<256>(sB[0], Bp, 128, tid);
    __pipeline_commit();
#pragma unroll
    for (int ck = 0; ck < 4; ck++) {
        if (ck + 1 < 4) {
            cpA<256>(sA[(ck + 1) & 1], A + (ck + 1) * 32, 128, rows_valid, tid);
            cpB<256>(sB[(ck + 1) & 1], Bp + (ck + 1) * 32 * 128, 128, tid);
            __pipeline_commit();
            __pipeline_wait_prior(1);
        } else {
            __pipeline_wait_prior(0);
        }
        __syncthreads();
        mma_chunk(sA[ck & 1], sB[ck & 1], cf, wm, wn);
        __syncthreads();
    }
#pragma unroll
    for (int i = 0; i < 2; i++)
#pragma unroll
        for (int j = 0; j < 4; j++)
            wmma::store_matrix_sync(sC + (wm * 32 + i * 16) * LDC + wn * 64 + j * 16,
                                    cf[i][j], LDC, wmma::mem_row_major);
    __syncthreads();
    float* outp = g_xdiff + ((size_t)b * Vn + row0) * 128;
#pragma unroll
    for (int it = 0; it < 16; it++) {
        int idx = tid + it * 256;
        int r = idx >> 5, c4 = (idx & 31) << 2;
        if (r < rows_valid)
            *(float4*)(outp + (size_t)r * 128 + c4) = *(float4*)(sC + r * LDC + c4);
    }
}

// ---------------------------------------------------------------------------
// 4) CSR build + gather (packed float4 edges)
// ---------------------------------------------------------------------------
__global__ __launch_bounds__(256) void k_hist(const int* __restrict__ rows) {
    int be = blockIdx.x * blockDim.x + threadIdx.x;
    if (be >= BE) return;
    int b = be / En;
    atomicAdd(&g_cnt[b * Vn + rows[be]], 1);
}
__global__ __launch_bounds__(512) void k_scanA() {
    __shared__ int s[512];
    int t = threadIdx.x;
    int i = blockIdx.x * 512 + t;
    int v = (i < BV) ? g_cnt[i] : 0;
    s[t] = v;
    __syncthreads();
#pragma unroll
    for (int d = 1; d < 512; d <<= 1) {
        int x = (t >= d) ? s[t - d] : 0;
        __syncthreads(); s[t] += x; __syncthreads();
    }
    if (i < BV) g_off[i] = s[t] - v;
    if (t == 511) g_bsum[blockIdx.x] = s[511];
}
__global__ __launch_bounds__(512) void k_scanB() {
    __shared__ int s[512];
    int t = threadIdx.x;
    int v = (t < NSCAN) ? g_bsum[t] : 0;
    s[t] = v;
    __syncthreads();
#pragma unroll
    for (int d = 1; d < 512; d <<= 1) {
        int x = (t >= d) ? s[t - d] : 0;
        __syncthreads(); s[t] += x; __syncthreads();
    }
    if (t < NSCAN) g_bsum[t] = s[t] - v;
}
__global__ __launch_bounds__(512) void k_scanC() {
    int i = blockIdx.x * 512 + threadIdx.x;
    if (i >= BV) return;
    int o = g_off[i] + g_bsum[blockIdx.x];
    g_off[i] = o;
    g_cur[i] = o;
}
__global__ __launch_bounds__(256) void k_scatter(const int* __restrict__ rows,
                                                 const int* __restrict__ cols,
                                                 const float* __restrict__ xv,
                                                 const float* __restrict__ yv) {
    int be = blockIdx.x * blockDim.x + threadIdx.x;
    if (be >= BE) return;
    int b = be / En;
    int pos = atomicAdd(&g_cur[b * Vn + rows[be]], 1);
    g_edge[pos] = make_float4(__int_as_float(cols[be]), xv[be], yv[be], 0.f);
}
// warp per row, float4 lanes, packed edge loads
__global__ __launch_bounds__(128) void k_gather() {
    const int w = threadIdx.x >> 5;
    const int lane = threadIdx.x & 31;
    const int flat = blockIdx.x * 4 + w;
    const int b = flat / Vn;
    const int start = g_off[flat];
    const int n = g_cnt[flat];
    const float4* __restrict__ xb = (const float4*)(g_xdiff + (size_t)b * Vn * 128);

    float4 ax = make_float4(0.f, 0.f, 0.f, 0.f);
    float4 ay = make_float4(0.f, 0.f, 0.f, 0.f);
    float4 ed = make_float4(__int_as_float(0), 0.f, 0.f, 0.f);
    if (n > 0) ed = g_edge[start];
    for (int e = 0; e < n; e++) {
        float4 edn = make_float4(__int_as_float(0), 0.f, 0.f, 0.f);
        if (e + 1 < n) edn = g_edge[start + e + 1];
        int col = __float_as_int(ed.x);
        float vx = ed.y, vy = ed.z;
        float4 x = xb[(size_t)col * 32 + lane];
        ax.x = fmaf(vx, x.x, ax.x); ax.y = fmaf(vx, x.y, ax.y);
        ax.z = fmaf(vx, x.z, ax.z); ax.w = fmaf(vx, x.w, ax.w);
        ay.x = fmaf(vy, x.x, ay.x); ay.y = fmaf(vy, x.y, ay.y);
        ay.z = fmaf(vy, x.z, ay.z); ay.w = fmaf(vy, x.w, ay.w);
        ed = edn;
    }
    *(float4*)(g_gx + (size_t)flat * 128 + lane * 4) = ax;
    *(float4*)(g_gy + (size_t)flat * 128 + lane * 4) = ay;
}

// ---------------------------------------------------------------------------
// 5) gradfeat: 512 threads, 4x4 warp grid, 32x32 per-warp tile, dual acc
// ---------------------------------------------------------------------------
__global__ __launch_bounds__(512) void g_gradfeat(const float* __restrict__ A_re,
                                                  const float* __restrict__ A_im) {
    extern __shared__ __align__(16) char sm[];
    float* base = (float*)sm;
    float* sGx[2] = {base, base + ABUF};
    float* sGy[2] = {base + 2 * ABUF, base + 3 * ABUF};
    float* sRe[2] = {base + 4 * ABUF, base + 4 * ABUF + BBUF};
    float* sIm[2] = {base + 4 * ABUF + 2 * BBUF, base + 4 * ABUF + 3 * BBUF};
    float* sCre = base;
    float* sCim = base + 128 * LDC;
    const int tid = threadIdx.x, wid = tid >> 5;
    const int wm = wid & 3, wn = wid >> 2;
    const size_t row0 = (size_t)blockIdx.x * 128;
    const int rows_valid = (int)min((size_t)128, (size_t)BV - row0);

    FragC cre[2][2], cim[2][2];
#pragma unroll
    for (int i = 0; i < 2; i++)
#pragma unroll
        for (int j = 0; j < 2; j++) {
            wmma::fill_fragment(cre[i][j], 0.f);
            wmma::fill_fragment(cim[i][j], 0.f);
        }

    if (rows_valid < 128) {
        zeroA2<512>(sGx[0], sGx[1], tid);
        zeroA2<512>(sGy[0], sGy[1], tid);
        __syncthreads();
    }

    cpA<512>(sGx[0], g_gx + row0 * 128, 128, rows_valid, tid);
    cpA<512>(sGy[0], g_gy + row0 * 128, 128, rows_valid, tid);
    cpB<512>(sRe[0], A_re, 128, tid);
    cpB<512>(sIm[0], A_im, 128, tid);
    __pipeline_commit();
#pragma unroll
    for (int ck = 0; ck < 4; ck++) {
        if (ck + 1 < 4) {
            int nb = (ck + 1) & 1;
            cpA<512>(sGx[nb], g_gx + row0 * 128 + (ck + 1) * 32, 128, rows_valid, tid);
            cpA<512>(sGy[nb], g_gy + row0 * 128 + (ck + 1) * 32, 128, rows_valid, tid);
            cpB<512>(sRe[nb], A_re + (ck + 1) * 32 * 128, 128, tid);
            cpB<512>(sIm[nb], A_im + (ck + 1) * 32 * 128, 128, tid);
            __pipeline_commit();
            __pipeline_wait_prior(1);
        } else {
            __pipeline_wait_prior(0);
        }
        __syncthreads();
        const int cb = ck & 1;
#pragma unroll
        for (int kk = 0; kk < 4; kk++) {
            FragA agx[2], agy[2], agyn[2];
            FragB bre[2], bim[2];
#pragma unroll
            for (int i = 0; i < 2; i++) {
                wmma::load_matrix_sync(agx[i], sGx[cb] + (wm * 32 + i * 16) * LDA + kk * 8, LDA);
                wmma::load_matrix_sync(agy[i], sGy[cb] + (wm * 32 + i * 16) * LDA + kk * 8, LDA);
                cvt_frag(agx[i]);
                cvt_frag(agy[i]);
#pragma unroll
                for (int e = 0; e < agy[i].num_elements; e++) agyn[i].x[e] = -agy[i].x[e];
            }
#pragma unroll
            for (int j = 0; j < 2; j++) {
                wmma::load_matrix_sync(bre[j], sRe[cb] + kk * 8 * LDB + wn * 32 + j * 16, LDB);
                wmma::load_matrix_sync(bim[j], sIm[cb] + kk * 8 * LDB + wn * 32 + j * 16, LDB);
                cvt_frag(bre[j]);
                cvt_frag(bim[j]);
            }
#pragma unroll
            for (int i = 0; i < 2; i++)
#pragma unroll
                for (int j = 0; j < 2; j++) {
                    wmma::mma_sync(cre[i][j], agx[i],  bre[j], cre[i][j]);
                    wmma::mma_sync(cre[i][j], agyn[i], bim[j], cre[i][j]);
                    wmma::mma_sync(cim[i][j], agy[i],  bre[j], cim[i][j]);
                    wmma::mma_sync(cim[i][j], agx[i],  bim[j], cim[i][j]);
                }
        }
        __syncthreads();
    }
#pragma unroll
    for (int i = 0; i < 2; i++)
#pragma unroll
        for (int j = 0; j < 2; j++) {
            wmma::store_matrix_sync(sCre + (wm * 32 + i * 16) * LDC + wn * 32 + j * 16,
                                    cre[i][j], LDC, wmma::mem_row_major);
            wmma::store_matrix_sync(sCim + (wm * 32 + i * 16) * LDC + wn * 32 + j * 16,
                                    cim[i][j], LDC, wmma::mem_row_major);
        }
    __syncthreads();
#pragma unroll
    for (int it = 0; it < 8; it++) {
        int idx = tid + it * 512;
        int r = idx >> 5, c4 = (idx & 31) << 2;
        if (r < rows_valid) {
            float4 re = *(float4*)(sCre + r * LDC + c4);
            float4 im = *(float4*)(sCim + r * LDC + c4);
            float4 gx4 = *(const float4*)(g_gx + (row0 + r) * 128 + c4);
            float4 gy4 = *(const float4*)(g_gy + (row0 + r) * 128 + c4);
            float4 o;
            o.x = tanhf(gx4.x * re.x + gy4.x * im.x);
            o.y = tanhf(gx4.y * re.y + gy4.y * im.y);
            o.z = tanhf(gx4.z * re.z + gy4.z * im.z);
            o.w = tanhf(gx4.w * re.w + gy4.w * im.w);
            *(float4*)(g_xgf + (row0 + r) * 128 + c4) = o;
        }
    }
}

// ---------------------------------------------------------------------------
// 6) mlp0 (cp.async): h = relu([x_in|xdiff|xgf] @ W0 + b0)
// ---------------------------------------------------------------------------
__global__ __launch_bounds__(256) void g_mlp0(const float* __restrict__ x_in,
                                              const float* __restrict__ W0,
                                              const float* __restrict__ b0) {
    extern __shared__ __align__(16) char sm[];
    float* sA[2] = {(float*)sm, (float*)sm + ABUF};
    float* sB[2] = {(float*)sm + 2 * ABUF, (float*)sm + 2 * ABUF + BBUF};
    float* sC = (float*)sm;
    const int tid = threadIdx.x, wid = tid >> 5;
    const int wm = wid & 3, wn = wid >> 2;
    const size_t row0 = (size_t)blockIdx.x * 128;
    const int rows_valid = (int)min((size_t)128, (size_t)BV - row0);

    FragC cf[2][4];
#pragma unroll
    for (int i = 0; i < 2; i++)
#pragma unroll
        for (int j = 0; j < 4; j++) wmma::fill_fragment(cf[i][j], 0.f);

    if (rows_valid < 128) { zeroA2<256>(sA[0], sA[1], tid); __syncthreads(); }

    const float* bases[3] = {x_in + row0 * 128, g_xdiff + row0 * 128, g_xgf + row0 * 128};

    cpA<256>(sA[0], bases[0], 128, rows_valid, tid);
    cpB<256>(sB[0], W0, 128, tid);
    __pipeline_commit();
    for (int ck = 0; ck < 12; ck++) {
        if (ck + 1 < 12) {
            int nc = ck + 1;
            cpA<256>(sA[nc & 1], bases[nc >> 2] + (nc & 3) * 32, 128, rows_valid, tid);
            cpB<256>(sB[nc & 1], W0 + (size_t)nc * 32 * 128, 128, tid);
            __pipeline_commit();
            __pipeline_wait_prior(1);
        } else {
            __pipeline_wait_prior(0);
        }
        __syncthreads();
        mma_chunk(sA[ck & 1], sB[ck & 1], cf, wm, wn);
        __syncthreads();
    }
#pragma unroll
    for (int i = 0; i < 2; i++)
#pragma unroll
        for (int j = 0; j < 4; j++)
            wmma::store_matrix_sync(sC + (wm * 32 + i * 16) * LDC + wn * 64 + j * 16,
                                    cf[i][j], LDC, wmma::mem_row_major);
    __syncthreads();
#pragma unroll
    for (int it = 0; it < 16; it++) {
        int idx = tid + it * 256;
        int r = idx >> 5, c4 = (idx & 31) << 2;
        if (r < rows_valid) {
            float4 v = *(float4*)(sC + r * LDC + c4);
            float4 bb = *(const float4*)(b0 + c4);
            float4 o;
            o.x = fmaxf(v.x + bb.x, 0.f);
            o.y = fmaxf(v.y + bb.y, 0.f);
            o.z = fmaxf(v.z + bb.z, 0.f);
            o.w = fmaxf(v.w + bb.w, 0.f);
            *(float4*)(g_h + (row0 + r) * 128 + c4) = o;
        }
    }
}

// ---------------------------------------------------------------------------
// 7) mlp1 (cp.async) + residual
// ---------------------------------------------------------------------------
__global__ __launch_bounds__(256) void g_mlp1(const float* __restrict__ x_in,
                                              const float* __restrict__ W1,
                                              const float* __restrict__ b1,
                                              float* __restrict__ out) {
    extern __shared__ __align__(16) char sm[];
    float* sA[2] = {(float*)sm, (float*)sm + ABUF};
    float* sB[2] = {(float*)sm + 2 * ABUF, (float*)sm + 2 * ABUF + BBUF};
    float* sC = (float*)sm;
    const int tid = threadIdx.x, wid = tid >> 5;
    const int wm = wid & 3, wn = wid >> 2;
    const size_t row0 = (size_t)blockIdx.x * 128;
    const int rows_valid = (int)min((size_t)128, (size_t)BV - row0);

    FragC cf[2][4];
#pragma unroll
    for (int i = 0; i < 2; i++)
#pragma unroll
        for (int j = 0; j < 4; j++) wmma::fill_fragment(cf[i][j], 0.f);

    if (rows_valid < 128) { zeroA2<256>(sA[0], sA[1], tid); __syncthreads(); }

    cpA<256>(sA[0], g_h + row0 * 128, 128, rows_valid, tid);
    cpB<256>(sB[0], W1, 128, tid);
    __pipeline_commit();
#pragma unroll
    for (int ck = 0; ck < 4; ck++) {
        if (ck + 1 < 4) {
            cpA<256>(sA[(ck + 1) & 1], g_h + row0 * 128 + (ck + 1) * 32, 128, rows_valid, tid);
            cpB<256>(sB[(ck + 1) & 1], W1 + (size_t)(ck + 1) * 32 * 128, 128, tid);
            __pipeline_commit();
            __pipeline_wait_prior(1);
        } else {
            __pipeline_wait_prior(0);
        }
        __syncthreads();
        mma_chunk(sA[ck & 1], sB[ck & 1], cf, wm, wn);
        __syncthreads();
    }
#pragma unroll
    for (int i = 0; i < 2; i++)
#pragma unroll
        for (int j = 0; j < 4; j++)
            wmma::store_matrix_sync(sC + (wm * 32 + i * 16) * LDC + wn * 64 + j * 16,
                                    cf[i][j], LDC, wmma::mem_row_major);
    __syncthreads();
#pragma unroll
    for (int it = 0; it < 16; it++) {
        int idx = tid + it * 256;
        int r = idx >> 5, c4 = (idx & 31) << 2;
        if (r < rows_valid) {
            float4 v = *(float4*)(sC + r * LDC + c4);
            float4 bb = *(const float4*)(b1 + c4);
            float4 xi = *(const float4*)(x_in + (row0 + r) * 128 + c4);
            *(float4*)(out + (row0 + r) * 128 + c4) =
                make_float4(v.x + bb.x + xi.x, v.y + bb.y + xi.y,
                            v.z + bb.z + xi.z, v.w + bb.w + xi.w);
        }
    }
}

// ---------------------------------------------------------------------------
// Launch: fork CSR chain onto a side stream, overlap with spectral chain
// ---------------------------------------------------------------------------
extern "C" void kernel_launch(void* const* d_in, const int* in_sizes, int n_in,
                              void* d_out, int out_size) {
    const float* x_in  = (const float*)d_in[0];
    const float* mass  = (const float*)d_in[1];
    const float* evals = (const float*)d_in[3];
    const float* evecs = (const float*)d_in[4];
    const int*   grows = (const int*)d_in[5];
    const int*   gcols = (const int*)d_in[6];
    const float* gxv   = (const float*)d_in[7];
    const float* gyv   = (const float*)d_in[8];
    const float* dt    = (const float*)d_in[9];
    const float* A_re  = (const float*)d_in[10];
    const float* A_im  = (const float*)d_in[11];
    const float* W0    = (const float*)d_in[12];
    const float* b0    = (const float*)d_in[13];
    const float* W1    = (const float*)d_in[14];
    const float* b1    = (const float*)d_in[15];
    float* out = (float*)d_out;

    static cudaStream_t s_csr = nullptr;
    static cudaEvent_t ev_fork = nullptr, ev_join = nullptr;
    if (s_csr == nullptr) {
        cudaStreamCreateWithFlags(&s_csr, cudaStreamNonBlocking);
        cudaEventCreateWithFlags(&ev_fork, cudaEventDisableTiming);
        cudaEventCreateWithFlags(&ev_join, cudaEventDisableTiming);
    }

    cudaFuncSetAttribute(k_project,  cudaFuncAttributeMaxDynamicSharedMemorySize, SMEM_PROJ);
    cudaFuncSetAttribute(g_diffuse,  cudaFuncAttributeMaxDynamicSharedMemorySize, SMEM_NORM);
    cudaFuncSetAttribute(g_gradfeat, cudaFuncAttributeMaxDynamicSharedMemorySize, SMEM_GRAD);
    cudaFuncSetAttribute(g_mlp0,     cudaFuncAttributeMaxDynamicSharedMemorySize, SMEM_NORM);
    cudaFuncSetAttribute(g_mlp1,     cudaFuncAttributeMaxDynamicSharedMemorySize, SMEM_NORM);

    // fork: CSR chain on side stream
    cudaEventRecord(ev_fork, 0);
    cudaStreamWaitEvent(s_csr, ev_fork, 0);
    k_zero_cnt<<<(BV + 255) / 256, 256, 0, s_csr>>>();
    k_hist<<<(BE + 255) / 256, 256, 0, s_csr>>>(grows);
    k_scanA<<<NSCAN, 512, 0, s_csr>>>();
    k_scanB<<<1, 512, 0, s_csr>>>();
    k_scanC<<<NSCAN, 512, 0, s_csr>>>();
    k_scatter<<<(BE + 255) / 256, 256, 0, s_csr>>>(grows, gcols, gxv, gyv);
    cudaEventRecord(ev_join, s_csr);

    // spectral chain on default stream (overlaps with CSR chain)
    k_zero_spec<<<(Bn * Kn * Cn + 255) / 256, 256>>>();
    k_project<<<dim3(GRIDP, Bn), 256, SMEM_PROJ>>>(x_in, mass, evecs);
    k_decay<<<(Bn * Kn * Cn + 255) / 256, 256>>>(evals, dt);
    g_diffuse<<<dim3(GRIDV, Bn), 256, SMEM_NORM>>>(evecs);

    // join: gather needs both chains
    cudaStreamWaitEvent(0, ev_join, 0);
    k_gather<<<BV / 4, 128>>>();

    g_gradfeat<<<GRIDM, 512, SMEM_GRAD>>>(A_re, A_im);
    g_mlp0<<<GRIDM, 256, SMEM_NORM>>>(x_in, W0, b0);
    g_mlp1<<<GRIDM, 256, SMEM_NORM>>>(x_in, W1, b1, out);
}

// round 7
// speedup vs baseline: 2.4254x; 1.0042x over previous
#include <cuda_runtime.h>
#include <cuda_pipeline.h>
#include <mma.h>
#include <math.h>
#include <stdint.h>

using namespace nvcuda;

#define Bn 4
#define Vn 50000
#define Cn 128
#define Kn 128
#define En 400000
#define BV (Bn * Vn)      // 200000
#define BE (Bn * En)      // 1600000
#define NSCAN 391
#define GRIDM 1563        // ceil(BV/128)
#define GRIDV 391         // ceil(Vn/128)
#define PROJ_VT 1024
#define GRIDP 49          // ceil(Vn/PROJ_VT)

// smem strides (floats)
#define LDA 36
#define LDB 136
#define LDE 132
#define LDC 132
#define ABUF (128 * LDA)   // 4608 floats
#define BBUF (32 * LDB)    // 4352 floats
#define SMEM_NORM (17920 * 4)    // 2*ABUF + 2*BBUF = 71680 B
#define SMEM_GRAD (35840 * 4)    // 4*ABUF + 4*BBUF = 143360 B
#define SM_E (32 * LDE * 4)
#define SMEM_PROJ (128 * LDC * 4)   // 67584 B

typedef wmma::fragment<wmma::matrix_a, 16, 16, 8, wmma::precision::tf32, wmma::row_major> FragA;
typedef wmma::fragment<wmma::matrix_a, 16, 16, 8, wmma::precision::tf32, wmma::col_major> FragAT;
typedef wmma::fragment<wmma::matrix_b, 16, 16, 8, wmma::precision::tf32, wmma::row_major> FragB;
typedef wmma::fragment<wmma::accumulator, 16, 16, 8, float> FragC;

// ---------------------------------------------------------------------------
// Scratch
// ---------------------------------------------------------------------------
__device__ __align__(16) float g_xspec[Bn * Kn * Cn];
__device__ __align__(16) float g_xdiff[(size_t)BV * Cn];
__device__ __align__(16) float g_gx[(size_t)BV * Cn];
__device__ __align__(16) float g_gy[(size_t)BV * Cn];
__device__ __align__(16) float g_xgf[(size_t)BV * Cn];
__device__ __align__(16) float g_h[(size_t)BV * Cn];

__device__ int    g_cnt[BV];
__device__ int    g_off[BV];
__device__ int    g_cur[BV];
__device__ int    g_bsum[NSCAN];
__device__ __align__(16) float4 g_edge[BE];   // {col(bits), vx, vy, unused}

// ---------------------------------------------------------------------------
// helpers
// ---------------------------------------------------------------------------
__device__ __forceinline__ float to_tf32(float x) { return wmma::__float_to_tf32(x); }

template<int NT>
__device__ __forceinline__ void cpA(float* sA, const float* __restrict__ g,
                                    int ld, int rows_valid, int tid) {
#pragma unroll
    for (int it = 0; it < 1024 / NT; it++) {
        int idx = tid + it * NT;
        int r = idx >> 3, c4 = (idx & 7) << 2;
        if (r < rows_valid)
            __pipeline_memcpy_async(sA + r * LDA + c4, g + (size_t)r * ld + c4, 16);
    }
}
template<int NT>
__device__ __forceinline__ void cpB(float* sB, const float* __restrict__ g,
                                    int ld, int tid) {
#pragma unroll
    for (int it = 0; it < 1024 / NT; it++) {
        int idx = tid + it * NT;
        int r = idx >> 5, c4 = (idx & 31) << 2;
        __pipeline_memcpy_async(sB + r * LDB + c4, g + (size_t)r * ld + c4, 16);
    }
}
template<int NT>
__device__ __forceinline__ void zeroA2(float* sA0, float* sA1, int tid) {
#pragma unroll
    for (int it = 0; it < (ABUF / 4 + NT - 1) / NT; it++) {
        int idx = (tid + it * NT) * 4;
        if (idx < ABUF) {
            *(float4*)(sA0 + idx) = make_float4(0.f, 0.f, 0.f, 0.f);
            *(float4*)(sA1 + idx) = make_float4(0.f, 0.f, 0.f, 0.f);
        }
    }
}
template<typename F>
__device__ __forceinline__ void cvt_frag(F& f) {
#pragma unroll
    for (int e = 0; e < f.num_elements; e++) f.x[e] = to_tf32(f.x[e]);
}

// ---------------------------------------------------------------------------
// zero kernels
// ---------------------------------------------------------------------------
__global__ void k_zero_spec() {
    int i = blockIdx.x * blockDim.x + threadIdx.x;
    if (i < Bn * Kn * Cn) g_xspec[i] = 0.f;
}
__global__ void k_zero_cnt() {
    int i = blockIdx.x * blockDim.x + threadIdx.x;
    if (i < BV) g_cnt[i] = 0;
}

// ---------------------------------------------------------------------------
// 1) projection (WMMA tf32)
// ---------------------------------------------------------------------------
__global__ __launch_bounds__(256) void k_project(const float* __restrict__ x_in,
                                                 const float* __restrict__ mass,
                                                 const float* __restrict__ evecs) {
    extern __shared__ __align__(16) char sm[];
    float* sE = (float*)sm;
    float* sX = (float*)(sm + SM_E);
    float* sC = (float*)sm;
    const int tid = threadIdx.x, wid = tid >> 5;
    const int wm = wid & 3, wn = wid >> 2;
    const int b = blockIdx.y;
    const int v0 = blockIdx.x * PROJ_VT;
    const int vend = min(v0 + PROJ_VT, Vn);

    FragC cf[2][4];
#pragma unroll
    for (int i = 0; i < 2; i++)
#pragma unroll
        for (int j = 0; j < 4; j++) wmma::fill_fragment(cf[i][j], 0.f);

    for (int vc = v0; vc < vend; vc += 32) {
        __syncthreads();
#pragma unroll
        for (int it = 0; it < 4; it++) {
            int idx = tid + it * 256;
            int r = idx >> 5, c4 = (idx & 31) << 2;
            int v = vc + r;
            float4 e4 = make_float4(0.f, 0.f, 0.f, 0.f);
            float4 x4 = make_float4(0.f, 0.f, 0.f, 0.f);
            if (v < Vn) {
                size_t base = ((size_t)b * Vn + v) * 128 + c4;
                e4 = *(const float4*)(evecs + base);
                float m = mass[b * Vn + v];
                x4 = *(const float4*)(x_in + base);
                x4.x *= m; x4.y *= m; x4.z *= m; x4.w *= m;
            }
            *(float4*)(sE + r * LDE + c4) =
                make_float4(to_tf32(e4.x), to_tf32(e4.y), to_tf32(e4.z), to_tf32(e4.w));
            *(float4*)(sX + r * LDB + c4) =
                make_float4(to_tf32(x4.x), to_tf32(x4.y), to_tf32(x4.z), to_tf32(x4.w));
        }
        __syncthreads();
#pragma unroll
        for (int kk = 0; kk < 4; kk++) {
            FragAT af[2];
            FragB bf[4];
#pragma unroll
            for (int i = 0; i < 2; i++)
                wmma::load_matrix_sync(af[i], sE + kk * 8 * LDE + wm * 32 + i * 16, LDE);
#pragma unroll
            for (int j = 0; j < 4; j++)
                wmma::load_matrix_sync(bf[j], sX + kk * 8 * LDB + wn * 64 + j * 16, LDB);
#pragma unroll
            for (int i = 0; i < 2; i++)
#pragma unroll
                for (int j = 0; j < 4; j++)
                    wmma::mma_sync(cf[i][j], af[i], bf[j], cf[i][j]);
        }
    }
    __syncthreads();
#pragma unroll
    for (int i = 0; i < 2; i++)
#pragma unroll
        for (int j = 0; j < 4; j++)
            wmma::store_matrix_sync(sC + (wm * 32 + i * 16) * LDC + wn * 64 + j * 16,
                                    cf[i][j], LDC, wmma::mem_row_major);
    __syncthreads();
    float* dst = g_xspec + (size_t)b * 16384;
#pragma unroll
    for (int it = 0; it < 16; it++) {
        int idx = tid + it * 256;
        int r = idx >> 5, c4 = (idx & 31) << 2;
        float4 v = *(float4*)(sC + r * LDC + c4);
        atomicAdd(&dst[r * 128 + c4 + 0], v.x);
        atomicAdd(&dst[r * 128 + c4 + 1], v.y);
        atomicAdd(&dst[r * 128 + c4 + 2], v.z);
        atomicAdd(&dst[r * 128 + c4 + 3], v.w);
    }
}

// ---------------------------------------------------------------------------
// 2) decay
// ---------------------------------------------------------------------------
__global__ void k_decay(const float* __restrict__ evals, const float* __restrict__ dt) {
    int i = blockIdx.x * blockDim.x + threadIdx.x;
    if (i >= Bn * Kn * Cn) return;
    int c = i & 127, k = (i >> 7) & 127, b = i >> 14;
    float t = fmaxf(dt[c], 1e-8f);
    g_xspec[i] *= expf(-evals[b * 128 + k] * t);
}

// ---------------------------------------------------------------------------
// MMA helper: one 32-wide K chunk on a 128x128 tile (256-thread kernels)
// ---------------------------------------------------------------------------
__device__ __forceinline__ void mma_chunk(const float* sA, const float* sB,
                                          FragC cf[2][4], int wm, int wn) {
#pragma unroll
    for (int kk = 0; kk < 4; kk++) {
        FragA af[2];
        FragB bf[4];
#pragma unroll
        for (int i = 0; i < 2; i++) {
            wmma::load_matrix_sync(af[i], sA + (wm * 32 + i * 16) * LDA + kk * 8, LDA);
            cvt_frag(af[i]);
        }
#pragma unroll
        for (int j = 0; j < 4; j++) {
            wmma::load_matrix_sync(bf[j], sB + kk * 8 * LDB + wn * 64 + j * 16, LDB);
            cvt_frag(bf[j]);
        }
#pragma unroll
        for (int i = 0; i < 2; i++)
#pragma unroll
            for (int j = 0; j < 4; j++)
                wmma::mma_sync(cf[i][j], af[i], bf[j], cf[i][j]);
    }
}

// ---------------------------------------------------------------------------
// 3) diffuse (cp.async double-buffered)
// ---------------------------------------------------------------------------
__global__ __launch_bounds__(256) void g_diffuse(const float* __restrict__ evecs) {
    extern __shared__ __align__(16) char sm[];
    float* sA[2] = {(float*)sm, (float*)sm + ABUF};
    float* sB[2] = {(float*)sm + 2 * ABUF, (float*)sm + 2 * ABUF + BBUF};
    float* sC = (float*)sm;
    const int tid = threadIdx.x, wid = tid >> 5;
    const int wm = wid & 3, wn = wid >> 2;
    const int b = blockIdx.y;
    const int row0 = blockIdx.x * 128;
    const int rows_valid = min(128, Vn - row0);
    const float* A = evecs + ((size_t)b * Vn + row0) * 128;
    const float* Bp = g_xspec + (size_t)b * 16384;

    FragC cf[2][4];
#pragma unroll
    for (int i = 0; i < 2; i++)
#pragma unroll
        for (int j = 0; j < 4; j++) wmma::fill_fragment(cf[i][j], 0.f);

    if (rows_valid < 128) { zeroA2<256>(sA[0], sA[1], tid); __syncthreads(); }

    cpA<256>(sA[0], A, 128, rows_valid, tid);
    cpB<256>(sB[0], Bp, 128, tid);
    __pipeline_commit();
#pragma unroll
    for (int ck = 0; ck < 4; ck++) {
        if (ck + 1 < 4) {
            cpA<256>(sA[(ck + 1) & 1], A + (ck + 1) * 32, 128, rows_valid, tid);
            cpB<256>(sB[(ck + 1) & 1], Bp + (ck + 1) * 32 * 128, 128, tid);
            __pipeline_commit();
            __pipeline_wait_prior(1);
        } else {
            __pipeline_wait_prior(0);
        }
        __syncthreads();
        mma_chunk(sA[ck & 1], sB[ck & 1], cf, wm, wn);
        __syncthreads();
    }
#pragma unroll
    for (int i = 0; i < 2; i++)
#pragma unroll
        for (int j = 0; j < 4; j++)
            wmma::store_matrix_sync(sC + (wm * 32 + i * 16) * LDC + wn * 64 + j * 16,
                                    cf[i][j], LDC, wmma::mem_row_major);
    __syncthreads();
    float* outp = g_xdiff + ((size_t)b * Vn + row0) * 128;
#pragma unroll
    for (int it = 0; it < 16; it++) {
        int idx = tid + it * 256;
        int r = idx >> 5, c4 = (idx & 31) << 2;
        if (r < rows_valid)
            *(float4*)(outp + (size_t)r * 128 + c4) = *(float4*)(sC + r * LDC + c4);
    }
}

// ---------------------------------------------------------------------------
// 4) CSR build + gather (packed float4 edges)
// ---------------------------------------------------------------------------
__global__ __launch_bounds__(256) void k_hist(const int* __restrict__ rows) {
    int be = blockIdx.x * blockDim.x + threadIdx.x;
    if (be >= BE) return;
    int b = be / En;
    atomicAdd(&g_cnt[b * Vn + rows[be]], 1);
}
__global__ __launch_bounds__(512) void k_scanA() {
    __shared__ int s[512];
    int t = threadIdx.x;
    int i = blockIdx.x * 512 + t;
    int v = (i < BV) ? g_cnt[i] : 0;
    s[t] = v;
    __syncthreads();
#pragma unroll
    for (int d = 1; d < 512; d <<= 1) {
        int x = (t >= d) ? s[t - d] : 0;
        __syncthreads(); s[t] += x; __syncthreads();
    }
    if (i < BV) g_off[i] = s[t] - v;
    if (t == 511) g_bsum[blockIdx.x] = s[511];
}
__global__ __launch_bounds__(512) void k_scanB() {
    __shared__ int s[512];
    int t = threadIdx.x;
    int v = (t < NSCAN) ? g_bsum[t] : 0;
    s[t] = v;
    __syncthreads();
#pragma unroll
    for (int d = 1; d < 512; d <<= 1) {
        int x = (t >= d) ? s[t - d] : 0;
        __syncthreads(); s[t] += x; __syncthreads();
    }
    if (t < NSCAN) g_bsum[t] = s[t] - v;
}
__global__ __launch_bounds__(512) void k_scanC() {
    int i = blockIdx.x * 512 + threadIdx.x;
    if (i >= BV) return;
    int o = g_off[i] + g_bsum[blockIdx.x];
    g_off[i] = o;
    g_cur[i] = o;
}
__global__ __launch_bounds__(256) void k_scatter(const int* __restrict__ rows,
                                                 const int* __restrict__ cols,
                                                 const float* __restrict__ xv,
                                                 const float* __restrict__ yv) {
    int be = blockIdx.x * blockDim.x + threadIdx.x;
    if (be >= BE) return;
    int b = be / En;
    int pos = atomicAdd(&g_cur[b * Vn + rows[be]], 1);
    g_edge[pos] = make_float4(__int_as_float(cols[be]), xv[be], yv[be], 0.f);
}
// warp per row, float4 lanes, packed edge loads
__global__ __launch_bounds__(128) void k_gather() {
    const int w = threadIdx.x >> 5;
    const int lane = threadIdx.x & 31;
    const int flat = blockIdx.x * 4 + w;
    const int b = flat / Vn;
    const int start = g_off[flat];
    const int n = g_cnt[flat];
    const float4* __restrict__ xb = (const float4*)(g_xdiff + (size_t)b * Vn * 128);

    float4 ax = make_float4(0.f, 0.f, 0.f, 0.f);
    float4 ay = make_float4(0.f, 0.f, 0.f, 0.f);
    float4 ed = make_float4(__int_as_float(0), 0.f, 0.f, 0.f);
    if (n > 0) ed = g_edge[start];
    for (int e = 0; e < n; e++) {
        float4 edn = make_float4(__int_as_float(0), 0.f, 0.f, 0.f);
        if (e + 1 < n) edn = g_edge[start + e + 1];
        int col = __float_as_int(ed.x);
        float vx = ed.y, vy = ed.z;
        float4 x = xb[(size_t)col * 32 + lane];
        ax.x = fmaf(vx, x.x, ax.x); ax.y = fmaf(vx, x.y, ax.y);
        ax.z = fmaf(vx, x.z, ax.z); ax.w = fmaf(vx, x.w, ax.w);
        ay.x = fmaf(vy, x.x, ay.x); ay.y = fmaf(vy, x.y, ay.y);
        ay.z = fmaf(vy, x.z, ay.z); ay.w = fmaf(vy, x.w, ay.w);
        ed = edn;
    }
    *(float4*)(g_gx + (size_t)flat * 128 + lane * 4) = ax;
    *(float4*)(g_gy + (size_t)flat * 128 + lane * 4) = ay;
}

// ---------------------------------------------------------------------------
// 5) gradfeat: 512 threads, 4x4 warp grid, 32x32 per-warp tile, dual acc
// ---------------------------------------------------------------------------
__global__ __launch_bounds__(512) void g_gradfeat(const float* __restrict__ A_re,
                                                  const float* __restrict__ A_im) {
    extern __shared__ __align__(16) char sm[];
    float* base = (float*)sm;
    float* sGx[2] = {base, base + ABUF};
    float* sGy[2] = {base + 2 * ABUF, base + 3 * ABUF};
    float* sRe[2] = {base + 4 * ABUF, base + 4 * ABUF + BBUF};
    float* sIm[2] = {base + 4 * ABUF + 2 * BBUF, base + 4 * ABUF + 3 * BBUF};
    float* sCre = base;
    float* sCim = base + 128 * LDC;
    const int tid = threadIdx.x, wid = tid >> 5;
    const int wm = wid & 3, wn = wid >> 2;
    const size_t row0 = (size_t)blockIdx.x * 128;
    const int rows_valid = (int)min((size_t)128, (size_t)BV - row0);

    FragC cre[2][2], cim[2][2];
#pragma unroll
    for (int i = 0; i < 2; i++)
#pragma unroll
        for (int j = 0; j < 2; j++) {
            wmma::fill_fragment(cre[i][j], 0.f);
            wmma::fill_fragment(cim[i][j], 0.f);
        }

    if (rows_valid < 128) {
        zeroA2<512>(sGx[0], sGx[1], tid);
        zeroA2<512>(sGy[0], sGy[1], tid);
        __syncthreads();
    }

    cpA<512>(sGx[0], g_gx + row0 * 128, 128, rows_valid, tid);
    cpA<512>(sGy[0], g_gy + row0 * 128, 128, rows_valid, tid);
    cpB<512>(sRe[0], A_re, 128, tid);
    cpB<512>(sIm[0], A_im, 128, tid);
    __pipeline_commit();
#pragma unroll
    for (int ck = 0; ck < 4; ck++) {
        if (ck + 1 < 4) {
            int nb = (ck + 1) & 1;
            cpA<512>(sGx[nb], g_gx + row0 * 128 + (ck + 1) * 32, 128, rows_valid, tid);
            cpA<512>(sGy[nb], g_gy + row0 * 128 + (ck + 1) * 32, 128, rows_valid, tid);
            cpB<512>(sRe[nb], A_re + (ck + 1) * 32 * 128, 128, tid);
            cpB<512>(sIm[nb], A_im + (ck + 1) * 32 * 128, 128, tid);
            __pipeline_commit();
            __pipeline_wait_prior(1);
        } else {
            __pipeline_wait_prior(0);
        }
        __syncthreads();
        const int cb = ck & 1;
#pragma unroll
        for (int kk = 0; kk < 4; kk++) {
            FragA agx[2], agy[2], agyn[2];
            FragB bre[2], bim[2];
#pragma unroll
            for (int i = 0; i < 2; i++) {
                wmma::load_matrix_sync(agx[i], sGx[cb] + (wm * 32 + i * 16) * LDA + kk * 8, LDA);
                wmma::load_matrix_sync(agy[i], sGy[cb] + (wm * 32 + i * 16) * LDA + kk * 8, LDA);
                cvt_frag(agx[i]);
                cvt_frag(agy[i]);
#pragma unroll
                for (int e = 0; e < agy[i].num_elements; e++) agyn[i].x[e] = -agy[i].x[e];
            }
#pragma unroll
            for (int j = 0; j < 2; j++) {
                wmma::load_matrix_sync(bre[j], sRe[cb] + kk * 8 * LDB + wn * 32 + j * 16, LDB);
                wmma::load_matrix_sync(bim[j], sIm[cb] + kk * 8 * LDB + wn * 32 + j * 16, LDB);
                cvt_frag(bre[j]);
                cvt_frag(bim[j]);
            }
#pragma unroll
            for (int i = 0; i < 2; i++)
#pragma unroll
                for (int j = 0; j < 2; j++) {
                    wmma::mma_sync(cre[i][j], agx[i],  bre[j], cre[i][j]);
                    wmma::mma_sync(cre[i][j], agyn[i], bim[j], cre[i][j]);
                    wmma::mma_sync(cim[i][j], agy[i],  bre[j], cim[i][j]);
                    wmma::mma_sync(cim[i][j], agx[i],  bim[j], cim[i][j]);
                }
        }
        __syncthreads();
    }
#pragma unroll
    for (int i = 0; i < 2; i++)
#pragma unroll
        for (int j = 0; j < 2; j++) {
            wmma::store_matrix_sync(sCre + (wm * 32 + i * 16) * LDC + wn * 32 + j * 16,
                                    cre[i][j], LDC, wmma::mem_row_major);
            wmma::store_matrix_sync(sCim + (wm * 32 + i * 16) * LDC + wn * 32 + j * 16,
                                    cim[i][j], LDC, wmma::mem_row_major);
        }
    __syncthreads();
#pragma unroll
    for (int it = 0; it < 8; it++) {
        int idx = tid + it * 512;
        int r = idx >> 5, c4 = (idx & 31) << 2;
        if (r < rows_valid) {
            float4 re = *(float4*)(sCre + r * LDC + c4);
            float4 im = *(float4*)(sCim + r * LDC + c4);
            float4 gx4 = *(const float4*)(g_gx + (row0 + r) * 128 + c4);
            float4 gy4 = *(const float4*)(g_gy + (row0 + r) * 128 + c4);
            float4 o;
            o.x = tanhf(gx4.x * re.x + gy4.x * im.x);
            o.y = tanhf(gx4.y * re.y + gy4.y * im.y);
            o.z = tanhf(gx4.z * re.z + gy4.z * im.z);
            o.w = tanhf(gx4.w * re.w + gy4.w * im.w);
            *(float4*)(g_xgf + (row0 + r) * 128 + c4) = o;
        }
    }
}

// ---------------------------------------------------------------------------
// 6) mlp0 (cp.async): h = relu([x_in|xdiff|xgf] @ W0 + b0)
// ---------------------------------------------------------------------------
__global__ __launch_bounds__(256) void g_mlp0(const float* __restrict__ x_in,
                                              const float* __restrict__ W0,
                                              const float* __restrict__ b0) {
    extern __shared__ __align__(16) char sm[];
    float* sA[2] = {(float*)sm, (float*)sm + ABUF};
    float* sB[2] = {(float*)sm + 2 * ABUF, (float*)sm + 2 * ABUF + BBUF};
    float* sC = (float*)sm;
    const int tid = threadIdx.x, wid = tid >> 5;
    const int wm = wid & 3, wn = wid >> 2;
    const size_t row0 = (size_t)blockIdx.x * 128;
    const int rows_valid = (int)min((size_t)128, (size_t)BV - row0);

    FragC cf[2][4];
#pragma unroll
    for (int i = 0; i < 2; i++)
#pragma unroll
        for (int j = 0; j < 4; j++) wmma::fill_fragment(cf[i][j], 0.f);

    if (rows_valid < 128) { zeroA2<256>(sA[0], sA[1], tid); __syncthreads(); }

    const float* bases[3] = {x_in + row0 * 128, g_xdiff + row0 * 128, g_xgf + row0 * 128};

    cpA<256>(sA[0], bases[0], 128, rows_valid, tid);
    cpB<256>(sB[0], W0, 128, tid);
    __pipeline_commit();
    for (int ck = 0; ck < 12; ck++) {
        if (ck + 1 < 12) {
            int nc = ck + 1;
            cpA<256>(sA[nc & 1], bases[nc >> 2] + (nc & 3) * 32, 128, rows_valid, tid);
            cpB<256>(sB[nc & 1], W0 + (size_t)nc * 32 * 128, 128, tid);
            __pipeline_commit();
            __pipeline_wait_prior(1);
        } else {
            __pipeline_wait_prior(0);
        }
        __syncthreads();
        mma_chunk(sA[ck & 1], sB[ck & 1], cf, wm, wn);
        __syncthreads();
    }
#pragma unroll
    for (int i = 0; i < 2; i++)
#pragma unroll
        for (int j = 0; j < 4; j++)
            wmma::store_matrix_sync(sC + (wm * 32 + i * 16) * LDC + wn * 64 + j * 16,
                                    cf[i][j], LDC, wmma::mem_row_major);
    __syncthreads();
#pragma unroll
    for (int it = 0; it < 16; it++) {
        int idx = tid + it * 256;
        int r = idx >> 5, c4 = (idx & 31) << 2;
        if (r < rows_valid) {
            float4 v = *(float4*)(sC + r * LDC + c4);
            float4 bb = *(const float4*)(b0 + c4);
            float4 o;
            o.x = fmaxf(v.x + bb.x, 0.f);
            o.y = fmaxf(v.y + bb.y, 0.f);
            o.z = fmaxf(v.z + bb.z, 0.f);
            o.w = fmaxf(v.w + bb.w, 0.f);
            *(float4*)(g_h + (row0 + r) * 128 + c4) = o;
        }
    }
}

// ---------------------------------------------------------------------------
// 7) mlp1 (cp.async) + residual
// ---------------------------------------------------------------------------
__global__ __launch_bounds__(256) void g_mlp1(const float* __restrict__ x_in,
                                              const float* __restrict__ W1,
                                              const float* __restrict__ b1,
                                              float* __restrict__ out) {
    extern __shared__ __align__(16) char sm[];
    float* sA[2] = {(float*)sm, (float*)sm + ABUF};
    float* sB[2] = {(float*)sm + 2 * ABUF, (float*)sm + 2 * ABUF + BBUF};
    float* sC = (float*)sm;
    const int tid = threadIdx.x, wid = tid >> 5;
    const int wm = wid & 3, wn = wid >> 2;
    const size_t row0 = (size_t)blockIdx.x * 128;
    const int rows_valid = (int)min((size_t)128, (size_t)BV - row0);

    FragC cf[2][4];
#pragma unroll
    for (int i = 0; i < 2; i++)
#pragma unroll
        for (int j = 0; j < 4; j++) wmma::fill_fragment(cf[i][j], 0.f);

    if (rows_valid < 128) { zeroA2<256>(sA[0], sA[1], tid); __syncthreads(); }

    cpA<256>(sA[0], g_h + row0 * 128, 128, rows_valid, tid);
    cpB<256>(sB[0], W1, 128, tid);
    __pipeline_commit();
#pragma unroll
    for (int ck = 0; ck < 4; ck++) {
        if (ck + 1 < 4) {
            cpA<256>(sA[(ck + 1) & 1], g_h + row0 * 128 + (ck + 1) * 32, 128, rows_valid, tid);
            cpB<256>(sB[(ck + 1) & 1], W1 + (size_t)(ck + 1) * 32 * 128, 128, tid);
            __pipeline_commit();
            __pipeline_wait_prior(1);
        } else {
            __pipeline_wait_prior(0);
        }
        __syncthreads();
        mma_chunk(sA[ck & 1], sB[ck & 1], cf, wm, wn);
        __syncthreads();
    }
#pragma unroll
    for (int i = 0; i < 2; i++)
#pragma unroll
        for (int j = 0; j < 4; j++)
            wmma::store_matrix_sync(sC + (wm * 32 + i * 16) * LDC + wn * 64 + j * 16,
                                    cf[i][j], LDC, wmma::mem_row_major);
    __syncthreads();
#pragma unroll
    for (int it = 0; it < 16; it++) {
        int idx = tid + it * 256;
        int r = idx >> 5, c4 = (idx & 31) << 2;
        if (r < rows_valid) {
            float4 v = *(float4*)(sC + r * LDC + c4);
            float4 bb = *(const float4*)(b1 + c4);
            float4 xi = *(const float4*)(x_in + (row0 + r) * 128 + c4);
            *(float4*)(out + (row0 + r) * 128 + c4) =
                make_float4(v.x + bb.x + xi.x, v.y + bb.y + xi.y,
                            v.z + bb.z + xi.z, v.w + bb.w + xi.w);
        }
    }
}

// ---------------------------------------------------------------------------
// Launch: fork CSR chain onto a side stream, overlap with spectral chain
// ---------------------------------------------------------------------------
extern "C" void kernel_launch(void* const* d_in, const int* in_sizes, int n_in,
                              void* d_out, int out_size) {
    const float* x_in  = (const float*)d_in[0];
    const float* mass  = (const float*)d_in[1];
    const float* evals = (const float*)d_in[3];
    const float* evecs = (const float*)d_in[4];
    const int*   grows = (const int*)d_in[5];
    const int*   gcols = (const int*)d_in[6];
    const float* gxv   = (const float*)d_in[7];
    const float* gyv   = (const float*)d_in[8];
    const float* dt    = (const float*)d_in[9];
    const float* A_re  = (const float*)d_in[10];
    const float* A_im  = (const float*)d_in[11];
    const float* W0    = (const float*)d_in[12];
    const float* b0    = (const float*)d_in[13];
    const float* W1    = (const float*)d_in[14];
    const float* b1    = (const float*)d_in[15];
    float* out = (float*)d_out;

    static cudaStream_t s_csr = nullptr;
    static cudaEvent_t ev_fork = nullptr, ev_join = nullptr;
    if (s_csr == nullptr) {
        cudaStreamCreateWithFlags(&s_csr, cudaStreamNonBlocking);
        cudaEventCreateWithFlags(&ev_fork, cudaEventDisableTiming);
        cudaEventCreateWithFlags(&ev_join, cudaEventDisableTiming);
    }

    cudaFuncSetAttribute(k_project,  cudaFuncAttributeMaxDynamicSharedMemorySize, SMEM_PROJ);
    cudaFuncSetAttribute(g_diffuse,  cudaFuncAttributeMaxDynamicSharedMemorySize, SMEM_NORM);
    cudaFuncSetAttribute(g_gradfeat, cudaFuncAttributeMaxDynamicSharedMemorySize, SMEM_GRAD);
    cudaFuncSetAttribute(g_mlp0,     cudaFuncAttributeMaxDynamicSharedMemorySize, SMEM_NORM);
    cudaFuncSetAttribute(g_mlp1,     cudaFuncAttributeMaxDynamicSharedMemorySize, SMEM_NORM);

    // fork: CSR chain on side stream
    cudaEventRecord(ev_fork, 0);
    cudaStreamWaitEvent(s_csr, ev_fork, 0);
    k_zero_cnt<<<(BV + 255) / 256, 256, 0, s_csr>>>();
    k_hist<<<(BE + 255) / 256, 256, 0, s_csr>>>(grows);
    k_scanA<<<NSCAN, 512, 0, s_csr>>>();
    k_scanB<<<1, 512, 0, s_csr>>>();
    k_scanC<<<NSCAN, 512, 0, s_csr>>>();
    k_scatter<<<(BE + 255) / 256, 256, 0, s_csr>>>(grows, gcols, gxv, gyv);
    cudaEventRecord(ev_join, s_csr);

    // spectral chain on default stream (overlaps with CSR chain)
    k_zero_spec<<<(Bn * Kn * Cn + 255) / 256, 256>>>();
    k_project<<<dim3(GRIDP, Bn), 256, SMEM_PROJ>>>(x_in, mass, evecs);
    k_decay<<<(Bn * Kn * Cn + 255) / 256, 256>>>(evals, dt);
    g_diffuse<<<dim3(GRIDV, Bn), 256, SMEM_NORM>>>(evecs);

    // join: gather needs both chains
    cudaStreamWaitEvent(0, ev_join, 0);
    k_gather<<<BV / 4, 128>>>();

    g_gradfeat<<<GRIDM, 512, SMEM_GRAD>>>(A_re, A_im);
    g_mlp0<<<GRIDM, 256, SMEM_NORM>>>(x_in, W0, b0);
    g_mlp1<<<GRIDM, 256, SMEM_NORM>>>(x_in, W1, b1, out);
}